// round 1
// baseline (speedup 1.0000x reference)
#include <cuda_runtime.h>
#include <math.h>

// ---------------- scratch (static device globals; no runtime allocation) ----
__device__ float g_h1[128 * 64 * 49 * 49];   // after conv1+pool+relu
__device__ float g_h2[128 * 128 * 23 * 23];  // after conv2+pool+relu
__device__ float g_h3[128 * 256 * 10 * 10];  // after conv3+pool+relu
__device__ float g_h4[128 * 512 * 4 * 4];    // after conv4+pool+relu (= fc input)
__device__ float g_fca[128 * 2048];          // fc1 out
__device__ float g_fcb[128 * 2048];          // fc2 out
__device__ float g_p[128 * 62];              // fc3 out
__device__ int   g_segi[128 * 20];           // per-(n,s) dict index
__device__ float g_segf[128 * 20 * 4];       // per-(n,s): ax, ay, startx, starty

// ---------------- conv1 (IC=3) + pool + relu --------------------------------
// in: x (128,3,100,100)  w (64,3,3,3)  out: (128,64,49,49)
__global__ void conv1_k(const float* __restrict__ x, const float* __restrict__ w,
                        const float* __restrict__ b, float* __restrict__ out) {
    __shared__ float sw[27];
    const int oc = blockIdx.y, n = blockIdx.z;
    if (threadIdx.x < 27) sw[threadIdx.x] = w[oc * 27 + threadIdx.x];
    __syncthreads();
    int pos = blockIdx.x * blockDim.x + threadIdx.x;
    if (pos >= 49 * 49) return;
    const int oy = pos / 49, ox = pos % 49;
    const float bias = b[oc];
    float a00 = bias, a01 = bias, a10 = bias, a11 = bias;
    const float* xin = x + n * 3 * 100 * 100 + (2 * oy) * 100 + 2 * ox;
#pragma unroll
    for (int ic = 0; ic < 3; ic++) {
        float p[4][4];
        const float* base = xin + ic * 10000;
#pragma unroll
        for (int r = 0; r < 4; r++)
#pragma unroll
            for (int c = 0; c < 4; c++) p[r][c] = base[r * 100 + c];
#pragma unroll
        for (int ky = 0; ky < 3; ky++)
#pragma unroll
            for (int kx = 0; kx < 3; kx++) {
                const float wv = sw[ic * 9 + ky * 3 + kx];
                a00 = fmaf(p[ky][kx],     wv, a00);
                a01 = fmaf(p[ky][kx + 1], wv, a01);
                a10 = fmaf(p[ky + 1][kx], wv, a10);
                a11 = fmaf(p[ky + 1][kx + 1], wv, a11);
            }
    }
    float m = fmaxf(fmaxf(a00, a01), fmaxf(a10, a11));
    out[((n * 64 + oc) * 49 + oy) * 49 + ox] = fmaxf(m, 0.f);
}

// ---------------- generic conv3x3 + pool2 + relu, 4 OC per thread -----------
template <int IC, int IN_H, int OUT_H, int OC>
__global__ void convpool_k(const float* __restrict__ in, const float* __restrict__ w,
                           const float* __restrict__ b, float* __restrict__ out) {
    extern __shared__ float sw[];  // 4 * IC * 9 floats
    const int ocg = blockIdx.y;
    const int tid = threadIdx.x;
    for (int i = tid; i < 4 * IC * 9; i += blockDim.x)
        sw[i] = w[ocg * 4 * IC * 9 + i];
    __syncthreads();

    const int item = blockIdx.x * blockDim.x + tid;
    if (item >= 128 * OUT_H * OUT_H) return;
    const int n = item / (OUT_H * OUT_H);
    const int pos = item % (OUT_H * OUT_H);
    const int oy = pos / OUT_H, ox = pos % OUT_H;

    float acc[4][4];
#pragma unroll
    for (int o = 0; o < 4; o++) {
        const float bias = b[ocg * 4 + o];
        acc[o][0] = bias; acc[o][1] = bias; acc[o][2] = bias; acc[o][3] = bias;
    }

    const float* xin = in + (size_t)n * IC * IN_H * IN_H + (2 * oy) * IN_H + 2 * ox;
    for (int ic = 0; ic < IC; ic++) {
        float p[4][4];
        const float* base = xin + ic * IN_H * IN_H;
#pragma unroll
        for (int r = 0; r < 4; r++)
#pragma unroll
            for (int c = 0; c < 4; c++) p[r][c] = __ldg(base + r * IN_H + c);
#pragma unroll
        for (int o = 0; o < 4; o++) {
            const float* wp = sw + (o * IC + ic) * 9;
#pragma unroll
            for (int ky = 0; ky < 3; ky++)
#pragma unroll
                for (int kx = 0; kx < 3; kx++) {
                    const float wv = wp[ky * 3 + kx];
                    acc[o][0] = fmaf(p[ky][kx],         wv, acc[o][0]);
                    acc[o][1] = fmaf(p[ky][kx + 1],     wv, acc[o][1]);
                    acc[o][2] = fmaf(p[ky + 1][kx],     wv, acc[o][2]);
                    acc[o][3] = fmaf(p[ky + 1][kx + 1], wv, acc[o][3]);
                }
        }
    }
#pragma unroll
    for (int o = 0; o < 4; o++) {
        float m = fmaxf(fmaxf(acc[o][0], acc[o][1]), fmaxf(acc[o][2], acc[o][3]));
        out[((n * OC + ocg * 4 + o) * OUT_H + oy) * OUT_H + ox] = fmaxf(m, 0.f);
    }
}

// ---------------- FC GEMM: C(128,N) = tanh(A(128,K) @ B(K,N) + bias) --------
// BM=32, BN=64, BK=16; 256 threads; 2x4 register tile per thread.
template <int K, int N, bool TANH>
__global__ void fc_k(const float* __restrict__ A, const float* __restrict__ B,
                     const float* __restrict__ bias, float* __restrict__ C) {
    __shared__ __align__(16) float As[16][32];
    __shared__ __align__(16) float Bs[16][64];
    const int tid = threadIdx.x;
    const int bm = blockIdx.x * 32, bn = blockIdx.y * 64;
    const int ty = tid / 16, tx = tid % 16;  // 16x16 thread grid
    const int row0 = ty * 2, col0 = tx * 4;

    float acc[2][4] = {{0.f, 0.f, 0.f, 0.f}, {0.f, 0.f, 0.f, 0.f}};

    for (int k0 = 0; k0 < K; k0 += 16) {
        // A tile: 32x16 = 512 elems, 2 per thread (consecutive k per thread)
#pragma unroll
        for (int i = 0; i < 2; i++) {
            const int idx = tid * 2 + i;
            const int m = idx >> 4, kk = idx & 15;
            As[kk][m] = A[(size_t)(bm + m) * K + k0 + kk];
        }
        // B tile: 16x64 = 1024 elems, 4 per thread (coalesced in n)
#pragma unroll
        for (int i = 0; i < 4; i++) {
            const int idx = tid * 4 + i;
            const int kk = idx >> 6, nn = idx & 63;
            Bs[kk][nn] = B[(size_t)(k0 + kk) * N + bn + nn];
        }
        __syncthreads();
#pragma unroll
        for (int kk = 0; kk < 16; kk++) {
            const float a0 = As[kk][row0], a1 = As[kk][row0 + 1];
            const float4 bv = *reinterpret_cast<const float4*>(&Bs[kk][col0]);
            acc[0][0] = fmaf(a0, bv.x, acc[0][0]);
            acc[0][1] = fmaf(a0, bv.y, acc[0][1]);
            acc[0][2] = fmaf(a0, bv.z, acc[0][2]);
            acc[0][3] = fmaf(a0, bv.w, acc[0][3]);
            acc[1][0] = fmaf(a1, bv.x, acc[1][0]);
            acc[1][1] = fmaf(a1, bv.y, acc[1][1]);
            acc[1][2] = fmaf(a1, bv.z, acc[1][2]);
            acc[1][3] = fmaf(a1, bv.w, acc[1][3]);
        }
        __syncthreads();
    }
#pragma unroll
    for (int i = 0; i < 2; i++)
#pragma unroll
        for (int j = 0; j < 4; j++) {
            float v = acc[i][j] + bias[bn + col0 + j];
            if (TANH) v = tanhf(v);
            C[(size_t)(bm + row0 + i) * N + bn + col0 + j] = v;
        }
}

// ---------------- fc3: (128,2048) @ (2048,62) + bias ------------------------
__global__ void fc3_k(const float* __restrict__ A, const float* __restrict__ W,
                      const float* __restrict__ bias, float* __restrict__ P) {
    __shared__ float sh[2048];
    const int n = blockIdx.x;
    for (int i = threadIdx.x; i < 2048; i += blockDim.x) sh[i] = A[n * 2048 + i];
    __syncthreads();
    const int j = threadIdx.x;
    if (j < 62) {
        float acc = bias[j];
#pragma unroll 4
        for (int k = 0; k < 2048; k++) acc = fmaf(sh[k], __ldg(W + k * 62 + j), acc);
        P[n * 62 + j] = acc;
    }
}

// ---------------- trajectory prep: per-n cumsum of segment offsets ----------
__global__ void trajprep_k(const float* __restrict__ P, const float* __restrict__ dict,
                           int* __restrict__ segi, float* __restrict__ segf) {
    const int n = blockIdx.x * blockDim.x + threadIdx.x;
    if (n >= 128) return;
    const float* p = P + n * 62;
    float sx = p[0], sy = p[1];
    for (int s = 0; s < 20; s++) {
        float f = rintf(p[2 + 3 * s]);        // round-half-to-even, like jnp.round
        f = fminf(fmaxf(f, 0.f), 999.f);
        const int idx = (int)f;
        const float a = p[2 + 3 * s + 1], bb = p[2 + 3 * s + 2];
        segi[n * 20 + s] = idx;
        segf[(n * 20 + s) * 4 + 0] = a;
        segf[(n * 20 + s) * 4 + 1] = bb;
        segf[(n * 20 + s) * 4 + 2] = sx;      // start = init + sum_{t<s} off_t
        segf[(n * 20 + s) * 4 + 3] = sy;
        sx = fmaf(dict[(idx * 200 + 199) * 2 + 0], a, sx);
        sy = fmaf(dict[(idx * 200 + 199) * 2 + 1], bb, sy);
    }
}

// ---------------- trajectory assembly ---------------------------------------
__global__ void traj_k(const float* __restrict__ dict, const int* __restrict__ segi,
                       const float* __restrict__ segf, float* __restrict__ out) {
    const int ns = blockIdx.x;   // 0..2559  (n*20+s)
    const int l = threadIdx.x;
    if (l >= 200) return;
    const int idx = segi[ns];
    const float a = segf[ns * 4 + 0], bb = segf[ns * 4 + 1];
    const float sx = segf[ns * 4 + 2], sy = segf[ns * 4 + 3];
    const float2 base = reinterpret_cast<const float2*>(dict)[idx * 200 + l];
    float2 o;
    o.x = fmaf(base.x, a, sx);
    o.y = fmaf(base.y, bb, sy);
    reinterpret_cast<float2*>(out)[ns * 200 + l] = o;
}

// ---------------- launcher ---------------------------------------------------
extern "C" void kernel_launch(void* const* d_in, const int* in_sizes, int n_in,
                              void* d_out, int out_size) {
    const float* x   = (const float*)d_in[0];
    const float* w1  = (const float*)d_in[1];
    const float* b1  = (const float*)d_in[2];
    const float* w2  = (const float*)d_in[3];
    const float* b2  = (const float*)d_in[4];
    const float* w3  = (const float*)d_in[5];
    const float* b3  = (const float*)d_in[6];
    const float* w4  = (const float*)d_in[7];
    const float* b4  = (const float*)d_in[8];
    const float* fw1 = (const float*)d_in[9];
    const float* fb1 = (const float*)d_in[10];
    const float* fw2 = (const float*)d_in[11];
    const float* fb2 = (const float*)d_in[12];
    const float* fw3 = (const float*)d_in[13];
    const float* fb3 = (const float*)d_in[14];
    const float* dict = (const float*)d_in[15];
    float* out = (float*)d_out;

    float *h1, *h2, *h3, *h4, *fca, *fcb, *p, *segf;
    int* segi;
    cudaGetSymbolAddress((void**)&h1,  g_h1);
    cudaGetSymbolAddress((void**)&h2,  g_h2);
    cudaGetSymbolAddress((void**)&h3,  g_h3);
    cudaGetSymbolAddress((void**)&h4,  g_h4);
    cudaGetSymbolAddress((void**)&fca, g_fca);
    cudaGetSymbolAddress((void**)&fcb, g_fcb);
    cudaGetSymbolAddress((void**)&p,   g_p);
    cudaGetSymbolAddress((void**)&segi, g_segi);
    cudaGetSymbolAddress((void**)&segf, g_segf);

    // conv1: (128,3,100,100) -> (128,64,49,49)
    {
        dim3 grid((49 * 49 + 255) / 256, 64, 128);
        conv1_k<<<grid, 256>>>(x, w1, b1, h1);
    }
    // conv2: (128,64,49,49) -> (128,128,23,23)
    {
        const int items = 128 * 23 * 23;
        dim3 grid((items + 255) / 256, 128 / 4);
        convpool_k<64, 49, 23, 128><<<grid, 256, 4 * 64 * 9 * sizeof(float)>>>(h1, w2, b2, h2);
    }
    // conv3: (128,128,23,23) -> (128,256,10,10)
    {
        const int items = 128 * 10 * 10;
        dim3 grid((items + 255) / 256, 256 / 4);
        convpool_k<128, 23, 10, 256><<<grid, 256, 4 * 128 * 9 * sizeof(float)>>>(h2, w3, b3, h3);
    }
    // conv4: (128,256,10,10) -> (128,512,4,4)
    {
        const int items = 128 * 4 * 4;
        dim3 grid((items + 255) / 256, 512 / 4);
        convpool_k<256, 10, 4, 512><<<grid, 256, 4 * 256 * 9 * sizeof(float)>>>(h3, w4, b4, h4);
    }
    // fc1: (128,8192)@(8192,2048) tanh
    fc_k<8192, 2048, true><<<dim3(4, 32), 256>>>(h4, fw1, fb1, fca);
    // fc2: (128,2048)@(2048,2048) tanh
    fc_k<2048, 2048, true><<<dim3(4, 32), 256>>>(fca, fw2, fb2, fcb);
    // fc3: (128,2048)@(2048,62)
    fc3_k<<<128, 64>>>(fcb, fw3, fb3, p);
    // trajectory
    trajprep_k<<<1, 128>>>(p, dict, segi, segf);
    traj_k<<<2560, 256>>>(dict, segi, segf, out);
}

// round 3
// speedup vs baseline: 1.5791x; 1.5791x over previous
#include <cuda_runtime.h>
#include <math.h>

// ---------------- scratch (static device globals; no runtime allocation) ----
// Padded row strides so float2 loads stay 8B-aligned.
__device__ float g_h1[128 * 64 * 49 * 50];   // conv1 out, stride 50
__device__ float g_h2[128 * 128 * 23 * 24];  // conv2 out, stride 24
__device__ float g_h3[128 * 256 * 10 * 10];  // conv3 out
__device__ float g_h4[128 * 512 * 4 * 4];    // conv4 out (= fc input)
__device__ float g_fca[128 * 2048];          // fc1 out
__device__ float g_fcb[128 * 2048];          // fc2 out
__device__ float g_p[128 * 62];              // fc3 out
__device__ int   g_segi[128 * 20];
__device__ float g_segf[128 * 20 * 4];

// ---------------- conv3x3 + pool2 + relu -------------------------------------
// Each thread: 2x2 pooled outputs (4x4 pre-pool window) x 4 output channels.
// Patch 6x6 loaded as float2 (8B aligned: input col base even, row stride even).
// Weights staged in smem; within a warp all lanes share ocg -> broadcast LDS.
template <int IC, int IN_H, int IN_S, int OUT_H, int OUT_S, int OC>
__global__ __launch_bounds__(256)
void convpool2_k(const float* __restrict__ in, const float* __restrict__ w,
                 const float* __restrict__ b, float* __restrict__ out) {
    extern __shared__ float sw[];  // 4 * IC * 9
    constexpr int T = (OUT_H + 1) / 2;
    constexpr int ITEMS = 128 * T * T;
    const int ocg = blockIdx.y;
    const int tid = threadIdx.x;
    for (int i = tid; i < 4 * IC * 9; i += 256)
        sw[i] = w[ocg * 4 * IC * 9 + i];
    __syncthreads();

    const int item = blockIdx.x * 256 + tid;
    if (item >= ITEMS) return;
    const int n = item / (T * T);
    const int r = item % (T * T);
    const int ty = r / T, tx = r % T;
    // clamp tile base so boundary tiles overlap (duplicate identical stores)
    const int py0 = min(2 * ty, OUT_H - 2);
    const int px0 = min(2 * tx, OUT_H - 2);
    const int iy0 = 2 * py0, ix0 = 2 * px0;

    float acc[4][16];
#pragma unroll
    for (int o = 0; o < 4; o++) {
        const float bias = __ldg(b + ocg * 4 + o);
#pragma unroll
        for (int q = 0; q < 16; q++) acc[o][q] = bias;
    }

    const float* base = in + (size_t)n * IC * IN_H * IN_S + iy0 * IN_S + ix0;
#pragma unroll 1
    for (int ic = 0; ic < IC; ic++) {
        float p[6][6];
        const float* bp = base + (size_t)ic * IN_H * IN_S;
#pragma unroll
        for (int rr = 0; rr < 6; rr++) {
            const float* rp = bp + rr * IN_S;
            const float2 v0 = *reinterpret_cast<const float2*>(rp);
            const float2 v1 = *reinterpret_cast<const float2*>(rp + 2);
            const float2 v2 = *reinterpret_cast<const float2*>(rp + 4);
            p[rr][0] = v0.x; p[rr][1] = v0.y;
            p[rr][2] = v1.x; p[rr][3] = v1.y;
            p[rr][4] = v2.x; p[rr][5] = v2.y;
        }
#pragma unroll
        for (int o = 0; o < 4; o++) {
            const float* wp = sw + (o * IC + ic) * 9;
#pragma unroll
            for (int ky = 0; ky < 3; ky++)
#pragma unroll
                for (int kx = 0; kx < 3; kx++) {
                    const float wv = wp[ky * 3 + kx];
#pragma unroll
                    for (int wy = 0; wy < 4; wy++)
#pragma unroll
                        for (int wx = 0; wx < 4; wx++)
                            acc[o][wy * 4 + wx] =
                                fmaf(p[wy + ky][wx + kx], wv, acc[o][wy * 4 + wx]);
                }
        }
    }

#pragma unroll
    for (int o = 0; o < 4; o++) {
        const int oc = ocg * 4 + o;
#pragma unroll
        for (int py = 0; py < 2; py++)
#pragma unroll
            for (int px = 0; px < 2; px++) {
                const float m = fmaxf(
                    fmaxf(acc[o][(2 * py) * 4 + 2 * px], acc[o][(2 * py) * 4 + 2 * px + 1]),
                    fmaxf(acc[o][(2 * py + 1) * 4 + 2 * px], acc[o][(2 * py + 1) * 4 + 2 * px + 1]));
                out[((size_t)(n * OC + oc) * OUT_H + (py0 + py)) * OUT_S + (px0 + px)] =
                    fmaxf(m, 0.f);
            }
    }
}

// ---------------- FC GEMM: C(128,N) = tanh(A(128,K) @ B(K,N) + bias) --------
template <int K, int N, bool TANH>
__global__ void fc_k(const float* __restrict__ A, const float* __restrict__ B,
                     const float* __restrict__ bias, float* __restrict__ C) {
    __shared__ __align__(16) float As[16][32];
    __shared__ __align__(16) float Bs[16][64];
    const int tid = threadIdx.x;
    const int bm = blockIdx.x * 32, bn = blockIdx.y * 64;
    const int ty = tid / 16, tx = tid % 16;
    const int row0 = ty * 2, col0 = tx * 4;

    float acc[2][4] = {{0.f, 0.f, 0.f, 0.f}, {0.f, 0.f, 0.f, 0.f}};

    for (int k0 = 0; k0 < K; k0 += 16) {
#pragma unroll
        for (int i = 0; i < 2; i++) {
            const int idx = tid * 2 + i;
            const int m = idx >> 4, kk = idx & 15;
            As[kk][m] = A[(size_t)(bm + m) * K + k0 + kk];
        }
#pragma unroll
        for (int i = 0; i < 4; i++) {
            const int idx = tid * 4 + i;
            const int kk = idx >> 6, nn = idx & 63;
            Bs[kk][nn] = B[(size_t)(k0 + kk) * N + bn + nn];
        }
        __syncthreads();
#pragma unroll
        for (int kk = 0; kk < 16; kk++) {
            const float a0 = As[kk][row0], a1 = As[kk][row0 + 1];
            const float4 bv = *reinterpret_cast<const float4*>(&Bs[kk][col0]);
            acc[0][0] = fmaf(a0, bv.x, acc[0][0]);
            acc[0][1] = fmaf(a0, bv.y, acc[0][1]);
            acc[0][2] = fmaf(a0, bv.z, acc[0][2]);
            acc[0][3] = fmaf(a0, bv.w, acc[0][3]);
            acc[1][0] = fmaf(a1, bv.x, acc[1][0]);
            acc[1][1] = fmaf(a1, bv.y, acc[1][1]);
            acc[1][2] = fmaf(a1, bv.z, acc[1][2]);
            acc[1][3] = fmaf(a1, bv.w, acc[1][3]);
        }
        __syncthreads();
    }
#pragma unroll
    for (int i = 0; i < 2; i++)
#pragma unroll
        for (int j = 0; j < 4; j++) {
            float v = acc[i][j] + bias[bn + col0 + j];
            if (TANH) v = tanhf(v);
            C[(size_t)(bm + row0 + i) * N + bn + col0 + j] = v;
        }
}

// ---------------- fc3: (128,2048) @ (2048,62) + bias ------------------------
// 256 threads: j = tid&63 (output col), c = tid>>6 (k-chunk of 512), smem reduce.
__global__ void fc3_k(const float* __restrict__ A, const float* __restrict__ W,
                      const float* __restrict__ bias, float* __restrict__ P) {
    __shared__ float sh[2048];
    __shared__ float red[4][64];
    const int n = blockIdx.x;
    for (int i = threadIdx.x; i < 2048; i += blockDim.x) sh[i] = A[n * 2048 + i];
    __syncthreads();
    const int j = threadIdx.x & 63;
    const int c = threadIdx.x >> 6;
    float acc = 0.f;
    if (j < 62) {
        const int k0 = c * 512;
#pragma unroll 8
        for (int k = 0; k < 512; k++)
            acc = fmaf(sh[k0 + k], __ldg(W + (size_t)(k0 + k) * 62 + j), acc);
    }
    red[c][j] = acc;
    __syncthreads();
    if (c == 0 && j < 62)
        P[n * 62 + j] = red[0][j] + red[1][j] + red[2][j] + red[3][j] + bias[j];
}

// ---------------- trajectory prep -------------------------------------------
__global__ void trajprep_k(const float* __restrict__ P, const float* __restrict__ dict,
                           int* __restrict__ segi, float* __restrict__ segf) {
    const int n = blockIdx.x * blockDim.x + threadIdx.x;
    if (n >= 128) return;
    const float* p = P + n * 62;
    float sx = p[0], sy = p[1];
    for (int s = 0; s < 20; s++) {
        float f = rintf(p[2 + 3 * s]);
        f = fminf(fmaxf(f, 0.f), 999.f);
        const int idx = (int)f;
        const float a = p[2 + 3 * s + 1], bb = p[2 + 3 * s + 2];
        segi[n * 20 + s] = idx;
        segf[(n * 20 + s) * 4 + 0] = a;
        segf[(n * 20 + s) * 4 + 1] = bb;
        segf[(n * 20 + s) * 4 + 2] = sx;
        segf[(n * 20 + s) * 4 + 3] = sy;
        sx = fmaf(dict[(idx * 200 + 199) * 2 + 0], a, sx);
        sy = fmaf(dict[(idx * 200 + 199) * 2 + 1], bb, sy);
    }
}

// ---------------- trajectory assembly ---------------------------------------
__global__ void traj_k(const float* __restrict__ dict, const int* __restrict__ segi,
                       const float* __restrict__ segf, float* __restrict__ out) {
    const int ns = blockIdx.x;
    const int l = threadIdx.x;
    if (l >= 200) return;
    const int idx = segi[ns];
    const float a = segf[ns * 4 + 0], bb = segf[ns * 4 + 1];
    const float sx = segf[ns * 4 + 2], sy = segf[ns * 4 + 3];
    const float2 base = reinterpret_cast<const float2*>(dict)[idx * 200 + l];
    float2 o;
    o.x = fmaf(base.x, a, sx);
    o.y = fmaf(base.y, bb, sy);
    reinterpret_cast<float2*>(out)[ns * 200 + l] = o;
}

// ---------------- launcher ---------------------------------------------------
extern "C" void kernel_launch(void* const* d_in, const int* in_sizes, int n_in,
                              void* d_out, int out_size) {
    const float* x   = (const float*)d_in[0];
    const float* w1  = (const float*)d_in[1];
    const float* b1  = (const float*)d_in[2];
    const float* w2  = (const float*)d_in[3];
    const float* b2  = (const float*)d_in[4];
    const float* w3  = (const float*)d_in[5];
    const float* b3  = (const float*)d_in[6];
    const float* w4  = (const float*)d_in[7];
    const float* b4  = (const float*)d_in[8];
    const float* fw1 = (const float*)d_in[9];
    const float* fb1 = (const float*)d_in[10];
    const float* fw2 = (const float*)d_in[11];
    const float* fb2 = (const float*)d_in[12];
    const float* fw3 = (const float*)d_in[13];
    const float* fb3 = (const float*)d_in[14];
    const float* dict = (const float*)d_in[15];
    float* out = (float*)d_out;

    float *h1, *h2, *h3, *h4, *fca, *fcb, *p, *segf;
    int* segi;
    cudaGetSymbolAddress((void**)&h1,  g_h1);
    cudaGetSymbolAddress((void**)&h2,  g_h2);
    cudaGetSymbolAddress((void**)&h3,  g_h3);
    cudaGetSymbolAddress((void**)&h4,  g_h4);
    cudaGetSymbolAddress((void**)&fca, g_fca);
    cudaGetSymbolAddress((void**)&fcb, g_fcb);
    cudaGetSymbolAddress((void**)&p,   g_p);
    cudaGetSymbolAddress((void**)&segi, g_segi);
    cudaGetSymbolAddress((void**)&segf, g_segf);

    // conv1: (128,3,100,100) -> (128,64,49x49 stride 50)   T=25
    {
        const int items = 128 * 25 * 25;
        convpool2_k<3, 100, 100, 49, 50, 64>
            <<<dim3((items + 255) / 256, 16), 256, 4 * 3 * 9 * sizeof(float)>>>(x, w1, b1, h1);
    }
    // conv2: -> (128,128,23x23 stride 24)   T=12
    {
        const int items = 128 * 12 * 12;
        convpool2_k<64, 49, 50, 23, 24, 128>
            <<<dim3((items + 255) / 256, 32), 256, 4 * 64 * 9 * sizeof(float)>>>(h1, w2, b2, h2);
    }
    // conv3: -> (128,256,10,10)   T=5
    {
        const int items = 128 * 5 * 5;
        convpool2_k<128, 23, 24, 10, 10, 256>
            <<<dim3((items + 255) / 256, 64), 256, 4 * 128 * 9 * sizeof(float)>>>(h2, w3, b3, h3);
    }
    // conv4: -> (128,512,4,4)   T=2
    {
        const int items = 128 * 2 * 2;
        convpool2_k<256, 10, 10, 4, 4, 512>
            <<<dim3((items + 255) / 256, 128), 256, 4 * 256 * 9 * sizeof(float)>>>(h3, w4, b4, h4);
    }
    // fc1: (128,8192)@(8192,2048) tanh
    fc_k<8192, 2048, true><<<dim3(4, 32), 256>>>(h4, fw1, fb1, fca);
    // fc2: (128,2048)@(2048,2048) tanh
    fc_k<2048, 2048, true><<<dim3(4, 32), 256>>>(fca, fw2, fb2, fcb);
    // fc3
    fc3_k<<<128, 256>>>(fcb, fw3, fb3, p);
    // trajectory
    trajprep_k<<<1, 128>>>(p, dict, segi, segf);
    traj_k<<<2560, 256>>>(dict, segi, segf, out);
}

// round 5
// speedup vs baseline: 1.6744x; 1.0603x over previous
#include <cuda_runtime.h>
#include <cuda_fp16.h>
#include <math.h>
#include <stdint.h>

// ---------------- scratch (static device globals; no runtime allocation) ----
__device__ float g_h1[128 * 64 * 49 * 50];
__device__ float g_h2[128 * 128 * 23 * 24];
__device__ float g_h3[128 * 256 * 10 * 10];
__device__ float g_h4[128 * 512 * 4 * 4];
__device__ float g_fcb[128 * 2048];          // fc2 out (fp32, fc3 input)
__device__ float g_p[128 * 62];
__device__ int   g_segi[128 * 20];
__device__ float g_segf[128 * 20 * 4];
// fp16-split buffers
__device__ __half g_A1hi[2048 * 8192];       // fw1^T scaled hi
__device__ __half g_A1lo[2048 * 8192];
__device__ __half g_A2hi[2048 * 2048];       // fw2^T scaled hi
__device__ __half g_A2lo[2048 * 2048];
__device__ __half g_B0hi[128 * 8192];        // h4 split
__device__ __half g_B0lo[128 * 8192];
__device__ __half g_B1hi[128 * 2048];        // fc1 out split
__device__ __half g_B1lo[128 * 2048];

#define WSCALE 1024.0f
#define WINV   (1.0f / 1024.0f)

// ---------------- conv3x3 + pool2 + relu (FFMA, proven) ---------------------
template <int IC, int IN_H, int IN_S, int OUT_H, int OUT_S, int OC>
__global__ __launch_bounds__(256)
void convpool2_k(const float* __restrict__ in, const float* __restrict__ w,
                 const float* __restrict__ b, float* __restrict__ out) {
    extern __shared__ float sw[];
    constexpr int T = (OUT_H + 1) / 2;
    constexpr int ITEMS = 128 * T * T;
    const int ocg = blockIdx.y;
    const int tid = threadIdx.x;
    for (int i = tid; i < 4 * IC * 9; i += 256)
        sw[i] = w[ocg * 4 * IC * 9 + i];
    __syncthreads();

    const int item = blockIdx.x * 256 + tid;
    if (item >= ITEMS) return;
    const int n = item / (T * T);
    const int r = item % (T * T);
    const int ty = r / T, tx = r % T;
    const int py0 = min(2 * ty, OUT_H - 2);
    const int px0 = min(2 * tx, OUT_H - 2);
    const int iy0 = 2 * py0, ix0 = 2 * px0;

    float acc[4][16];
#pragma unroll
    for (int o = 0; o < 4; o++) {
        const float bias = __ldg(b + ocg * 4 + o);
#pragma unroll
        for (int q = 0; q < 16; q++) acc[o][q] = bias;
    }

    const float* base = in + (size_t)n * IC * IN_H * IN_S + iy0 * IN_S + ix0;
#pragma unroll 1
    for (int ic = 0; ic < IC; ic++) {
        float p[6][6];
        const float* bp = base + (size_t)ic * IN_H * IN_S;
#pragma unroll
        for (int rr = 0; rr < 6; rr++) {
            const float* rp = bp + rr * IN_S;
            const float2 v0 = *reinterpret_cast<const float2*>(rp);
            const float2 v1 = *reinterpret_cast<const float2*>(rp + 2);
            const float2 v2 = *reinterpret_cast<const float2*>(rp + 4);
            p[rr][0] = v0.x; p[rr][1] = v0.y;
            p[rr][2] = v1.x; p[rr][3] = v1.y;
            p[rr][4] = v2.x; p[rr][5] = v2.y;
        }
#pragma unroll
        for (int o = 0; o < 4; o++) {
            const float* wp = sw + (o * IC + ic) * 9;
#pragma unroll
            for (int ky = 0; ky < 3; ky++)
#pragma unroll
                for (int kx = 0; kx < 3; kx++) {
                    const float wv = wp[ky * 3 + kx];
#pragma unroll
                    for (int wy = 0; wy < 4; wy++)
#pragma unroll
                        for (int wx = 0; wx < 4; wx++)
                            acc[o][wy * 4 + wx] =
                                fmaf(p[wy + ky][wx + kx], wv, acc[o][wy * 4 + wx]);
                }
        }
    }

#pragma unroll
    for (int o = 0; o < 4; o++) {
        const int oc = ocg * 4 + o;
#pragma unroll
        for (int py = 0; py < 2; py++)
#pragma unroll
            for (int px = 0; px < 2; px++) {
                const float m = fmaxf(
                    fmaxf(acc[o][(2 * py) * 4 + 2 * px], acc[o][(2 * py) * 4 + 2 * px + 1]),
                    fmaxf(acc[o][(2 * py + 1) * 4 + 2 * px], acc[o][(2 * py + 1) * 4 + 2 * px + 1]));
                out[((size_t)(n * OC + oc) * OUT_H + (py0 + py)) * OUT_S + (px0 + px)] =
                    fmaxf(m, 0.f);
            }
    }
}

// ---------------- weight transpose + scale + fp16 split ---------------------
// W[K][M] fp32 -> A_hi/A_lo[M][K] fp16, scaled by WSCALE.
__global__ void wsplit_k(const float* __restrict__ W, __half* __restrict__ Ahi,
                         __half* __restrict__ Alo, int Kdim, int Mdim) {
    __shared__ float t[32][33];
    const int m0 = blockIdx.x * 32, k0 = blockIdx.y * 32;
    const int tx = threadIdx.x, ty = threadIdx.y;  // 32 x 8
#pragma unroll
    for (int j = 0; j < 4; j++)
        t[ty + 8 * j][tx] = W[(size_t)(k0 + ty + 8 * j) * Mdim + m0 + tx];
    __syncthreads();
#pragma unroll
    for (int j = 0; j < 4; j++) {
        const int m = m0 + ty + 8 * j, k = k0 + tx;
        const float v = t[tx][ty + 8 * j] * WSCALE;
        const __half hi = __float2half_rn(v);
        const __half lo = __float2half_rn(v - __half2float(hi));
        Ahi[(size_t)m * Kdim + k] = hi;
        Alo[(size_t)m * Kdim + k] = lo;
    }
}

// ---------------- activation fp16 split (elementwise) -----------------------
__global__ void hsplit_k(const float* __restrict__ in, __half* __restrict__ hi,
                         __half* __restrict__ lo, int n) {
    const int i = blockIdx.x * 256 + threadIdx.x;
    if (i >= n) return;
    const float v = in[i];
    const __half h = __float2half_rn(v);
    hi[i] = h;
    lo[i] = __float2half_rn(v - __half2float(h));
}

// ---------------- mma.sync m16n8k16 wrapper ---------------------------------
__device__ __forceinline__ void mma16816(float* c, const uint32_t* a, const uint32_t* b) {
    asm volatile(
        "mma.sync.aligned.m16n8k16.row.col.f32.f16.f16.f32 "
        "{%0,%1,%2,%3}, {%4,%5,%6,%7}, {%8,%9}, {%0,%1,%2,%3};"
        : "+f"(c[0]), "+f"(c[1]), "+f"(c[2]), "+f"(c[3])
        : "r"(a[0]), "r"(a[1]), "r"(a[2]), "r"(a[3]), "r"(b[0]), "r"(b[1]));
}

// ---------------- HMMA fp16-split FC GEMM -----------------------------------
// C[m][n] = tanh( WINV * sum_k A[m,k]*B[n,k] + bias[m] ),  N = 128 batch.
// Block: 128 M-rows; 8 warps as 4(M) x 2(N); warp tile 32x64.
// smem: 4 tiles [128 rows][64 halfs], row stride 144B (9 int4) -> conflict-free.
template <int K>
__global__ __launch_bounds__(256)
void gemm_fc_mma(const __half* __restrict__ Ahi, const __half* __restrict__ Alo,
                 const __half* __restrict__ Bhi, const __half* __restrict__ Blo,
                 const float* __restrict__ bias, int M_TOTAL,
                 __half* __restrict__ out_hi, __half* __restrict__ out_lo,
                 float* __restrict__ out_f32) {
    extern __shared__ __align__(16) char smem[];
    constexpr int TILE = 128 * 144;            // bytes per tile
    constexpr int ROWI4 = K / 8;               // int4 per global row
    const int tid = threadIdx.x;
    const int wid = tid >> 5, lane = tid & 31;
    const int gid = lane >> 2, tig = lane & 3;
    const int warpM = wid & 3, warpN = wid >> 2;
    const int m0 = blockIdx.x * 128;

    const int4* srcs[4] = {
        reinterpret_cast<const int4*>(Ahi) + (size_t)m0 * ROWI4,
        reinterpret_cast<const int4*>(Alo) + (size_t)m0 * ROWI4,
        reinterpret_cast<const int4*>(Bhi),
        reinterpret_cast<const int4*>(Blo)};

    float acc[2][8][4];
#pragma unroll
    for (int mt = 0; mt < 2; mt++)
#pragma unroll
        for (int nt = 0; nt < 8; nt++)
#pragma unroll
            for (int q = 0; q < 4; q++) acc[mt][nt][q] = 0.f;

    for (int ch = 0; ch < K / 64; ch++) {
        // stage 4 tiles: 128 rows x 8 int4 each
#pragma unroll
        for (int r = 0; r < 4; r++) {
            const int4* src = srcs[r] + ch * 8;
#pragma unroll
            for (int j = 0; j < 4; j++) {
                const int u = j * 256 + tid;
                const int row = u >> 3, c = u & 7;
                *reinterpret_cast<int4*>(smem + r * TILE + row * 144 + c * 16) =
                    src[(size_t)row * ROWI4 + c];
            }
        }
        __syncthreads();

#pragma unroll
        for (int ks = 0; ks < 4; ks++) {
            uint32_t ah[2][4], al[2][4], bh[8][2], bl[8][2];
#pragma unroll
            for (int mt = 0; mt < 2; mt++) {
                const int row = warpM * 32 + mt * 16 + gid;
                const char* pA = smem + row * 144 + ks * 32 + tig * 4;
                ah[mt][0] = *reinterpret_cast<const uint32_t*>(pA);
                ah[mt][1] = *reinterpret_cast<const uint32_t*>(pA + 8 * 144);
                ah[mt][2] = *reinterpret_cast<const uint32_t*>(pA + 16);
                ah[mt][3] = *reinterpret_cast<const uint32_t*>(pA + 8 * 144 + 16);
                const char* pL = pA + TILE;
                al[mt][0] = *reinterpret_cast<const uint32_t*>(pL);
                al[mt][1] = *reinterpret_cast<const uint32_t*>(pL + 8 * 144);
                al[mt][2] = *reinterpret_cast<const uint32_t*>(pL + 16);
                al[mt][3] = *reinterpret_cast<const uint32_t*>(pL + 8 * 144 + 16);
            }
#pragma unroll
            for (int nt = 0; nt < 8; nt++) {
                const int n = warpN * 64 + nt * 8 + gid;
                const char* pB = smem + 2 * TILE + n * 144 + ks * 32 + tig * 4;
                bh[nt][0] = *reinterpret_cast<const uint32_t*>(pB);
                bh[nt][1] = *reinterpret_cast<const uint32_t*>(pB + 16);
                bl[nt][0] = *reinterpret_cast<const uint32_t*>(pB + TILE);
                bl[nt][1] = *reinterpret_cast<const uint32_t*>(pB + TILE + 16);
            }
#pragma unroll
            for (int mt = 0; mt < 2; mt++)
#pragma unroll
                for (int nt = 0; nt < 8; nt++) {
                    mma16816(acc[mt][nt], ah[mt], bh[nt]);
                    mma16816(acc[mt][nt], ah[mt], bl[nt]);
                    mma16816(acc[mt][nt], al[mt], bh[nt]);
                }
        }
        __syncthreads();
    }

    // epilogue: C fragment rows = M, cols = N
#pragma unroll
    for (int mt = 0; mt < 2; mt++) {
        const int mA = m0 + warpM * 32 + mt * 16 + gid;
        const int mB = mA + 8;
        const float bA = bias[mA], bB = bias[mB];
#pragma unroll
        for (int nt = 0; nt < 8; nt++) {
            const int n0 = warpN * 64 + nt * 8 + tig * 2;
#pragma unroll
            for (int half = 0; half < 2; half++) {
                const int n = n0 + half;
                const float vA = tanhf(acc[mt][nt][half] * WINV + bA);
                const float vB = tanhf(acc[mt][nt][2 + half] * WINV + bB);
                if (out_f32) {
                    out_f32[(size_t)n * M_TOTAL + mA] = vA;
                    out_f32[(size_t)n * M_TOTAL + mB] = vB;
                }
                if (out_hi) {
                    const __half hA = __float2half_rn(vA);
                    const __half hB = __float2half_rn(vB);
                    out_hi[(size_t)n * M_TOTAL + mA] = hA;
                    out_lo[(size_t)n * M_TOTAL + mA] = __float2half_rn(vA - __half2float(hA));
                    out_hi[(size_t)n * M_TOTAL + mB] = hB;
                    out_lo[(size_t)n * M_TOTAL + mB] = __float2half_rn(vB - __half2float(hB));
                }
            }
        }
    }
}

// ---------------- fc3 (FFMA fp32) -------------------------------------------
__global__ void fc3_k(const float* __restrict__ A, const float* __restrict__ W,
                      const float* __restrict__ bias, float* __restrict__ P) {
    __shared__ float sh[2048];
    __shared__ float red[4][64];
    const int n = blockIdx.x;
    for (int i = threadIdx.x; i < 2048; i += blockDim.x) sh[i] = A[n * 2048 + i];
    __syncthreads();
    const int j = threadIdx.x & 63;
    const int c = threadIdx.x >> 6;
    float acc = 0.f;
    if (j < 62) {
        const int k0 = c * 512;
#pragma unroll 8
        for (int k = 0; k < 512; k++)
            acc = fmaf(sh[k0 + k], __ldg(W + (size_t)(k0 + k) * 62 + j), acc);
    }
    red[c][j] = acc;
    __syncthreads();
    if (c == 0 && j < 62)
        P[n * 62 + j] = red[0][j] + red[1][j] + red[2][j] + red[3][j] + bias[j];
}

// ---------------- trajectory ------------------------------------------------
__global__ void trajprep_k(const float* __restrict__ P, const float* __restrict__ dict,
                           int* __restrict__ segi, float* __restrict__ segf) {
    const int n = blockIdx.x * blockDim.x + threadIdx.x;
    if (n >= 128) return;
    const float* p = P + n * 62;
    float sx = p[0], sy = p[1];
    for (int s = 0; s < 20; s++) {
        float f = rintf(p[2 + 3 * s]);
        f = fminf(fmaxf(f, 0.f), 999.f);
        const int idx = (int)f;
        const float a = p[2 + 3 * s + 1], bb = p[2 + 3 * s + 2];
        segi[n * 20 + s] = idx;
        segf[(n * 20 + s) * 4 + 0] = a;
        segf[(n * 20 + s) * 4 + 1] = bb;
        segf[(n * 20 + s) * 4 + 2] = sx;
        segf[(n * 20 + s) * 4 + 3] = sy;
        sx = fmaf(dict[(idx * 200 + 199) * 2 + 0], a, sx);
        sy = fmaf(dict[(idx * 200 + 199) * 2 + 1], bb, sy);
    }
}

__global__ void traj_k(const float* __restrict__ dict, const int* __restrict__ segi,
                       const float* __restrict__ segf, float* __restrict__ out) {
    const int ns = blockIdx.x;
    const int l = threadIdx.x;
    if (l >= 200) return;
    const int idx = segi[ns];
    const float a = segf[ns * 4 + 0], bb = segf[ns * 4 + 1];
    const float sx = segf[ns * 4 + 2], sy = segf[ns * 4 + 3];
    const float2 base = reinterpret_cast<const float2*>(dict)[idx * 200 + l];
    float2 o;
    o.x = fmaf(base.x, a, sx);
    o.y = fmaf(base.y, bb, sy);
    reinterpret_cast<float2*>(out)[ns * 200 + l] = o;
}

// ---------------- launcher ---------------------------------------------------
extern "C" void kernel_launch(void* const* d_in, const int* in_sizes, int n_in,
                              void* d_out, int out_size) {
    const float* x   = (const float*)d_in[0];
    const float* w1  = (const float*)d_in[1];
    const float* b1  = (const float*)d_in[2];
    const float* w2  = (const float*)d_in[3];
    const float* b2  = (const float*)d_in[4];
    const float* w3  = (const float*)d_in[5];
    const float* b3  = (const float*)d_in[6];
    const float* w4  = (const float*)d_in[7];
    const float* b4  = (const float*)d_in[8];
    const float* fw1 = (const float*)d_in[9];
    const float* fb1 = (const float*)d_in[10];
    const float* fw2 = (const float*)d_in[11];
    const float* fb2 = (const float*)d_in[12];
    const float* fw3 = (const float*)d_in[13];
    const float* fb3 = (const float*)d_in[14];
    const float* dict = (const float*)d_in[15];
    float* out = (float*)d_out;

    float *h1, *h2, *h3, *h4, *fcb, *p, *segf;
    int* segi;
    __half *A1hi, *A1lo, *A2hi, *A2lo, *B0hi, *B0lo, *B1hi, *B1lo;
    cudaGetSymbolAddress((void**)&h1,  g_h1);
    cudaGetSymbolAddress((void**)&h2,  g_h2);
    cudaGetSymbolAddress((void**)&h3,  g_h3);
    cudaGetSymbolAddress((void**)&h4,  g_h4);
    cudaGetSymbolAddress((void**)&fcb, g_fcb);
    cudaGetSymbolAddress((void**)&p,   g_p);
    cudaGetSymbolAddress((void**)&segi, g_segi);
    cudaGetSymbolAddress((void**)&segf, g_segf);
    cudaGetSymbolAddress((void**)&A1hi, g_A1hi);
    cudaGetSymbolAddress((void**)&A1lo, g_A1lo);
    cudaGetSymbolAddress((void**)&A2hi, g_A2hi);
    cudaGetSymbolAddress((void**)&A2lo, g_A2lo);
    cudaGetSymbolAddress((void**)&B0hi, g_B0hi);
    cudaGetSymbolAddress((void**)&B0lo, g_B0lo);
    cudaGetSymbolAddress((void**)&B1hi, g_B1hi);
    cudaGetSymbolAddress((void**)&B1lo, g_B1lo);

    cudaFuncSetAttribute(gemm_fc_mma<8192>, cudaFuncAttributeMaxDynamicSharedMemorySize, 73728);
    cudaFuncSetAttribute(gemm_fc_mma<2048>, cudaFuncAttributeMaxDynamicSharedMemorySize, 73728);

    // conv1
    {
        const int items = 128 * 25 * 25;
        convpool2_k<3, 100, 100, 49, 50, 64>
            <<<dim3((items + 255) / 256, 16), 256, 4 * 3 * 9 * sizeof(float)>>>(x, w1, b1, h1);
    }
    // weight prep for fc1/fc2
    wsplit_k<<<dim3(2048 / 32, 8192 / 32), dim3(32, 8)>>>(fw1, A1hi, A1lo, 8192, 2048);
    wsplit_k<<<dim3(2048 / 32, 2048 / 32), dim3(32, 8)>>>(fw2, A2hi, A2lo, 2048, 2048);
    // conv2
    {
        const int items = 128 * 12 * 12;
        convpool2_k<64, 49, 50, 23, 24, 128>
            <<<dim3((items + 255) / 256, 32), 256, 4 * 64 * 9 * sizeof(float)>>>(h1, w2, b2, h2);
    }
    // conv3
    {
        const int items = 128 * 5 * 5;
        convpool2_k<128, 23, 24, 10, 10, 256>
            <<<dim3((items + 255) / 256, 64), 256, 4 * 128 * 9 * sizeof(float)>>>(h2, w3, b3, h3);
    }
    // conv4
    {
        const int items = 128 * 2 * 2;
        convpool2_k<256, 10, 10, 4, 4, 512>
            <<<dim3((items + 255) / 256, 128), 256, 4 * 256 * 9 * sizeof(float)>>>(h3, w4, b4, h4);
    }
    // split h4 for fc1
    hsplit_k<<<(128 * 8192 + 255) / 256, 256>>>(h4, B0hi, B0lo, 128 * 8192);
    // fc1: HMMA GEMM -> fp16 split (fc2 input)
    gemm_fc_mma<8192><<<16, 256, 73728>>>(A1hi, A1lo, B0hi, B0lo, fb1, 2048,
                                          B1hi, B1lo, (float*)nullptr);
    // fc2: HMMA GEMM -> fp32 (fc3 input)
    gemm_fc_mma<2048><<<16, 256, 73728>>>(A2hi, A2lo, B1hi, B1lo, fb2, 2048,
                                          (__half*)nullptr, (__half*)nullptr, fcb);
    // fc3 (fp32 FFMA)
    fc3_k<<<128, 256>>>(fcb, fw3, fb3, p);
    // trajectory
    trajprep_k<<<1, 128>>>(p, dict, segi, segf);
    traj_k<<<2560, 256>>>(dict, segi, segf, out);
}

// round 6
// speedup vs baseline: 1.7748x; 1.0599x over previous
#include <cuda_runtime.h>
#include <cuda_fp16.h>
#include <math.h>
#include <stdint.h>

#define WSCALE 1024.0f
#define WINV   (1.0f / 1024.0f)

// ---------------- scratch (static device globals) ---------------------------
__device__ __half g_h1hi[128 * 64 * 49 * 49];
__device__ __half g_h1lo[128 * 64 * 49 * 49];
__device__ float  g_pre2[128 * 128 * 47 * 47];
__device__ __half g_h2hi[128 * 128 * 23 * 23];
__device__ __half g_h2lo[128 * 128 * 23 * 23];
__device__ float  g_pre3[128 * 256 * 21 * 21];
__device__ __half g_h3hi[128 * 256 * 10 * 10];
__device__ __half g_h3lo[128 * 256 * 10 * 10];
__device__ float  g_pre4[128 * 512 * 8 * 8];
__device__ __half g_W2hi[128 * 576],  g_W2lo[128 * 576];
__device__ __half g_W3hi[256 * 1152], g_W3lo[256 * 1152];
__device__ __half g_W4hi[512 * 2304], g_W4lo[512 * 2304];
__device__ float  g_fcb[128 * 2048];
__device__ float  g_p[128 * 62];
__device__ int    g_segi[128 * 20];
__device__ float  g_segf[128 * 20 * 4];
__device__ __half g_A1hi[2048 * 8192], g_A1lo[2048 * 8192];
__device__ __half g_A2hi[2048 * 2048], g_A2lo[2048 * 2048];
__device__ __half g_B0hi[128 * 8192],  g_B0lo[128 * 8192];
__device__ __half g_B1hi[128 * 2048],  g_B1lo[128 * 2048];

// ---------------- conv1 (IC=3, FFMA) + pool + relu + fp16 split -------------
__global__ __launch_bounds__(256)
void conv1split_k(const float* __restrict__ in, const float* __restrict__ w,
                  const float* __restrict__ b, __half* __restrict__ hi,
                  __half* __restrict__ lo) {
    __shared__ float sw[108];
    const int ocg = blockIdx.y, tid = threadIdx.x;
    if (tid < 108) sw[tid] = w[ocg * 108 + tid];
    __syncthreads();
    const int item = blockIdx.x * 256 + tid;
    if (item >= 128 * 25 * 25) return;
    const int n = item / 625, r = item % 625;
    const int ty = r / 25, tx = r % 25;
    const int py0 = min(2 * ty, 47), px0 = min(2 * tx, 47);
    const int iy0 = 2 * py0, ix0 = 2 * px0;

    float acc[4][16];
#pragma unroll
    for (int o = 0; o < 4; o++) {
        const float bias = __ldg(b + ocg * 4 + o);
#pragma unroll
        for (int q = 0; q < 16; q++) acc[o][q] = bias;
    }
    const float* base = in + (size_t)n * 3 * 10000 + iy0 * 100 + ix0;
#pragma unroll
    for (int ic = 0; ic < 3; ic++) {
        float p[6][6];
        const float* bp = base + ic * 10000;
#pragma unroll
        for (int rr = 0; rr < 6; rr++) {
            const float* rp = bp + rr * 100;
            const float2 v0 = *reinterpret_cast<const float2*>(rp);
            const float2 v1 = *reinterpret_cast<const float2*>(rp + 2);
            const float2 v2 = *reinterpret_cast<const float2*>(rp + 4);
            p[rr][0] = v0.x; p[rr][1] = v0.y; p[rr][2] = v1.x;
            p[rr][3] = v1.y; p[rr][4] = v2.x; p[rr][5] = v2.y;
        }
#pragma unroll
        for (int o = 0; o < 4; o++) {
            const float* wp = sw + (o * 3 + ic) * 9;
#pragma unroll
            for (int ky = 0; ky < 3; ky++)
#pragma unroll
                for (int kx = 0; kx < 3; kx++) {
                    const float wv = wp[ky * 3 + kx];
#pragma unroll
                    for (int wy = 0; wy < 4; wy++)
#pragma unroll
                        for (int wx = 0; wx < 4; wx++)
                            acc[o][wy * 4 + wx] =
                                fmaf(p[wy + ky][wx + kx], wv, acc[o][wy * 4 + wx]);
                }
        }
    }
#pragma unroll
    for (int o = 0; o < 4; o++) {
        const int oc = ocg * 4 + o;
#pragma unroll
        for (int py = 0; py < 2; py++)
#pragma unroll
            for (int px = 0; px < 2; px++) {
                const float m = fmaxf(
                    fmaxf(acc[o][(2 * py) * 4 + 2 * px], acc[o][(2 * py) * 4 + 2 * px + 1]),
                    fmaxf(acc[o][(2 * py + 1) * 4 + 2 * px], acc[o][(2 * py + 1) * 4 + 2 * px + 1]));
                const float v = fmaxf(m, 0.f);
                const size_t addr = ((size_t)(n * 64 + oc) * 49 + py0 + py) * 49 + px0 + px;
                const __half h = __float2half_rn(v);
                hi[addr] = h;
                lo[addr] = __float2half_rn(v - __half2float(h));
            }
    }
}

// ---------------- weight split (elementwise, conv layout) -------------------
__global__ void wsplitc_k(const float* __restrict__ W, __half* __restrict__ hi,
                          __half* __restrict__ lo, int n) {
    const int i = blockIdx.x * 256 + threadIdx.x;
    if (i >= n) return;
    const float v = W[i] * WSCALE;
    const __half h = __float2half_rn(v);
    hi[i] = h;
    lo[i] = __float2half_rn(v - __half2float(h));
}

// ---------------- weight transpose + scale + split (FC) ---------------------
__global__ void wsplit_k(const float* __restrict__ W, __half* __restrict__ Ahi,
                         __half* __restrict__ Alo, int Kdim, int Mdim) {
    __shared__ float t[32][33];
    const int m0 = blockIdx.x * 32, k0 = blockIdx.y * 32;
    const int tx = threadIdx.x, ty = threadIdx.y;
#pragma unroll
    for (int j = 0; j < 4; j++)
        t[ty + 8 * j][tx] = W[(size_t)(k0 + ty + 8 * j) * Mdim + m0 + tx];
    __syncthreads();
#pragma unroll
    for (int j = 0; j < 4; j++) {
        const int m = m0 + ty + 8 * j, k = k0 + tx;
        const float v = t[tx][ty + 8 * j] * WSCALE;
        const __half hi = __float2half_rn(v);
        const __half lo = __float2half_rn(v - __half2float(hi));
        Ahi[(size_t)m * Kdim + k] = hi;
        Alo[(size_t)m * Kdim + k] = lo;
    }
}

// ---------------- mma.sync m16n8k16 wrapper ---------------------------------
__device__ __forceinline__ void mma16816(float* c, const uint32_t* a, const uint32_t* b) {
    asm volatile(
        "mma.sync.aligned.m16n8k16.row.col.f32.f16.f16.f32 "
        "{%0,%1,%2,%3}, {%4,%5,%6,%7}, {%8,%9}, {%0,%1,%2,%3};"
        : "+f"(c[0]), "+f"(c[1]), "+f"(c[2]), "+f"(c[3])
        : "r"(a[0]), "r"(a[1]), "r"(a[2]), "r"(a[3]), "r"(b[0]), "r"(b[1]));
}

// ---------------- implicit-GEMM conv (HMMA fp16-split) ----------------------
// pre[n][oc][oy*PH+ox] = WINV * sum_k W[oc,k]*im2col[k, col] + bias[oc]
// A = split weights [OC][IC*9]; B = im2col of split activations.
template <int IC, int IN_H, int IN_S, int PH, int OC>
__global__ __launch_bounds__(256)
void conv_mma_k(const __half* __restrict__ Whi, const __half* __restrict__ Wlo,
                const __half* __restrict__ inhi, const __half* __restrict__ inlo,
                const float* __restrict__ bias, float* __restrict__ pre) {
    extern __shared__ __align__(16) char smem[];
    constexpr int K = IC * 9;
    constexpr int PHH = PH * PH;
    constexpr int TILE = 128 * 144;
    constexpr int ROWI4 = K / 8;
    const int tid = threadIdx.x;
    const int wid = tid >> 5, lane = tid & 31;
    const int gid = lane >> 2, tig = lane & 3;
    const int warpM = wid & 3, warpN = wid >> 2;
    const int m0 = blockIdx.y * 128;

    __shared__ int s_bo[128];  // input base offset per col
    __shared__ int s_ob[128];  // output base per col
    if (tid < 128) {
        const int col = blockIdx.x * 128 + tid;
        const int n = col / PHH, rem = col % PHH;
        const int oy = rem / PH, ox = rem % PH;
        s_bo[tid] = ((n * IC) * IN_H + oy) * IN_S + ox;
        s_ob[tid] = n * OC * PHH + rem;
    }
    __syncthreads();

    float acc[2][8][4];
#pragma unroll
    for (int mt = 0; mt < 2; mt++)
#pragma unroll
        for (int nt = 0; nt < 8; nt++)
#pragma unroll
            for (int q = 0; q < 4; q++) acc[mt][nt][q] = 0.f;

    const int4* Ah4 = reinterpret_cast<const int4*>(Whi) + (size_t)m0 * ROWI4;
    const int4* Al4 = reinterpret_cast<const int4*>(Wlo) + (size_t)m0 * ROWI4;

    for (int ch = 0; ch < K / 64; ch++) {
        // A tiles: 128 rows x 8 int4
#pragma unroll
        for (int j = 0; j < 4; j++) {
            const int u = j * 256 + tid;
            const int row = u >> 3, c = u & 7;
            *reinterpret_cast<int4*>(smem + 0 * TILE + row * 144 + c * 16) =
                Ah4[(size_t)row * ROWI4 + ch * 8 + c];
            *reinterpret_cast<int4*>(smem + 1 * TILE + row * 144 + c * 16) =
                Al4[(size_t)row * ROWI4 + ch * 8 + c];
        }
        // B tiles: inline im2col, 64 kk-rows x 128 cols, hi+lo
#pragma unroll 8
        for (int i = 0; i < 32; i++) {
            const int u = i * 256 + tid;
            const int kr = u >> 7, j = u & 127;
            const int kk = ch * 64 + kr;
            const int ic = kk / 9, r9 = kk % 9;
            const int ky = r9 / 3, kx = r9 % 3;
            const int off = s_bo[j] + (ic * IN_H + ky) * IN_S + kx;
            *reinterpret_cast<__half*>(smem + 2 * TILE + j * 144 + kr * 2) = inhi[off];
            *reinterpret_cast<__half*>(smem + 3 * TILE + j * 144 + kr * 2) = inlo[off];
        }
        __syncthreads();

#pragma unroll
        for (int ks = 0; ks < 4; ks++) {
            uint32_t ah[2][4], al[2][4], bh[8][2], bl[8][2];
#pragma unroll
            for (int mt = 0; mt < 2; mt++) {
                const int row = warpM * 32 + mt * 16 + gid;
                const char* pA = smem + row * 144 + ks * 32 + tig * 4;
                ah[mt][0] = *reinterpret_cast<const uint32_t*>(pA);
                ah[mt][1] = *reinterpret_cast<const uint32_t*>(pA + 8 * 144);
                ah[mt][2] = *reinterpret_cast<const uint32_t*>(pA + 16);
                ah[mt][3] = *reinterpret_cast<const uint32_t*>(pA + 8 * 144 + 16);
                const char* pL = pA + TILE;
                al[mt][0] = *reinterpret_cast<const uint32_t*>(pL);
                al[mt][1] = *reinterpret_cast<const uint32_t*>(pL + 8 * 144);
                al[mt][2] = *reinterpret_cast<const uint32_t*>(pL + 16);
                al[mt][3] = *reinterpret_cast<const uint32_t*>(pL + 8 * 144 + 16);
            }
#pragma unroll
            for (int nt = 0; nt < 8; nt++) {
                const int n = warpN * 64 + nt * 8 + gid;
                const char* pB = smem + 2 * TILE + n * 144 + ks * 32 + tig * 4;
                bh[nt][0] = *reinterpret_cast<const uint32_t*>(pB);
                bh[nt][1] = *reinterpret_cast<const uint32_t*>(pB + 16);
                bl[nt][0] = *reinterpret_cast<const uint32_t*>(pB + TILE);
                bl[nt][1] = *reinterpret_cast<const uint32_t*>(pB + TILE + 16);
            }
#pragma unroll
            for (int mt = 0; mt < 2; mt++)
#pragma unroll
                for (int nt = 0; nt < 8; nt++) {
                    mma16816(acc[mt][nt], ah[mt], bh[nt]);
                    mma16816(acc[mt][nt], ah[mt], bl[nt]);
                    mma16816(acc[mt][nt], al[mt], bh[nt]);
                }
        }
        __syncthreads();
    }

    // epilogue: scatter pre-pool conv values (bias included)
#pragma unroll
    for (int mt = 0; mt < 2; mt++) {
        const int ocA = m0 + warpM * 32 + mt * 16 + gid;
        const int ocB = ocA + 8;
        const float bA = bias[ocA], bB = bias[ocB];
#pragma unroll
        for (int nt = 0; nt < 8; nt++) {
#pragma unroll
            for (int half = 0; half < 2; half++) {
                const int j = warpN * 64 + nt * 8 + tig * 2 + half;
                pre[(size_t)s_ob[j] + (size_t)ocA * PHH] = acc[mt][nt][half] * WINV + bA;
                pre[(size_t)s_ob[j] + (size_t)ocB * PHH] = acc[mt][nt][2 + half] * WINV + bB;
            }
        }
    }
}

// ---------------- pool2x2 + relu + fp16 split -------------------------------
template <int OC, int PH, int OH, int FC_LAYOUT>
__global__ void poolsplit_k(const float* __restrict__ pre, __half* __restrict__ hi,
                            __half* __restrict__ lo) {
    constexpr int PHH = PH * PH;
    const int idx = blockIdx.x * 256 + threadIdx.x;
    if (idx >= 128 * OC * OH * OH) return;
    const int ox = idx % OH;
    int t = idx / OH;
    const int oy = t % OH; t /= OH;
    const int oc = t % OC;
    const int n = t / OC;
    const float* p = pre + (size_t)(n * OC + oc) * PHH + (2 * oy) * PH + 2 * ox;
    const float m = fmaxf(fmaxf(p[0], p[1]), fmaxf(p[PH], p[PH + 1]));
    const float v = fmaxf(m, 0.f);
    const __half h = __float2half_rn(v);
    const __half l = __float2half_rn(v - __half2float(h));
    size_t o;
    if (FC_LAYOUT) o = (size_t)n * (OC * OH * OH) + (size_t)oc * (OH * OH) + oy * OH + ox;
    else           o = ((size_t)(n * OC + oc) * OH + oy) * OH + ox;
    hi[o] = h;
    lo[o] = l;
}

// ---------------- HMMA fp16-split FC GEMM (proven R5 core) ------------------
template <int K>
__global__ __launch_bounds__(256)
void gemm_fc_mma(const __half* __restrict__ Ahi, const __half* __restrict__ Alo,
                 const __half* __restrict__ Bhi, const __half* __restrict__ Blo,
                 const float* __restrict__ bias, int M_TOTAL,
                 __half* __restrict__ out_hi, __half* __restrict__ out_lo,
                 float* __restrict__ out_f32) {
    extern __shared__ __align__(16) char smem[];
    constexpr int TILE = 128 * 144;
    constexpr int ROWI4 = K / 8;
    const int tid = threadIdx.x;
    const int wid = tid >> 5, lane = tid & 31;
    const int gid = lane >> 2, tig = lane & 3;
    const int warpM = wid & 3, warpN = wid >> 2;
    const int m0 = blockIdx.x * 128;

    const int4* srcs[4] = {
        reinterpret_cast<const int4*>(Ahi) + (size_t)m0 * ROWI4,
        reinterpret_cast<const int4*>(Alo) + (size_t)m0 * ROWI4,
        reinterpret_cast<const int4*>(Bhi),
        reinterpret_cast<const int4*>(Blo)};

    float acc[2][8][4];
#pragma unroll
    for (int mt = 0; mt < 2; mt++)
#pragma unroll
        for (int nt = 0; nt < 8; nt++)
#pragma unroll
            for (int q = 0; q < 4; q++) acc[mt][nt][q] = 0.f;

    for (int ch = 0; ch < K / 64; ch++) {
#pragma unroll
        for (int r = 0; r < 4; r++) {
            const int4* src = srcs[r] + ch * 8;
#pragma unroll
            for (int j = 0; j < 4; j++) {
                const int u = j * 256 + tid;
                const int row = u >> 3, c = u & 7;
                *reinterpret_cast<int4*>(smem + r * TILE + row * 144 + c * 16) =
                    src[(size_t)row * ROWI4 + c];
            }
        }
        __syncthreads();

#pragma unroll
        for (int ks = 0; ks < 4; ks++) {
            uint32_t ah[2][4], al[2][4], bh[8][2], bl[8][2];
#pragma unroll
            for (int mt = 0; mt < 2; mt++) {
                const int row = warpM * 32 + mt * 16 + gid;
                const char* pA = smem + row * 144 + ks * 32 + tig * 4;
                ah[mt][0] = *reinterpret_cast<const uint32_t*>(pA);
                ah[mt][1] = *reinterpret_cast<const uint32_t*>(pA + 8 * 144);
                ah[mt][2] = *reinterpret_cast<const uint32_t*>(pA + 16);
                ah[mt][3] = *reinterpret_cast<const uint32_t*>(pA + 8 * 144 + 16);
                const char* pL = pA + TILE;
                al[mt][0] = *reinterpret_cast<const uint32_t*>(pL);
                al[mt][1] = *reinterpret_cast<const uint32_t*>(pL + 8 * 144);
                al[mt][2] = *reinterpret_cast<const uint32_t*>(pL + 16);
                al[mt][3] = *reinterpret_cast<const uint32_t*>(pL + 8 * 144 + 16);
            }
#pragma unroll
            for (int nt = 0; nt < 8; nt++) {
                const int n = warpN * 64 + nt * 8 + gid;
                const char* pB = smem + 2 * TILE + n * 144 + ks * 32 + tig * 4;
                bh[nt][0] = *reinterpret_cast<const uint32_t*>(pB);
                bh[nt][1] = *reinterpret_cast<const uint32_t*>(pB + 16);
                bl[nt][0] = *reinterpret_cast<const uint32_t*>(pB + TILE);
                bl[nt][1] = *reinterpret_cast<const uint32_t*>(pB + TILE + 16);
            }
#pragma unroll
            for (int mt = 0; mt < 2; mt++)
#pragma unroll
                for (int nt = 0; nt < 8; nt++) {
                    mma16816(acc[mt][nt], ah[mt], bh[nt]);
                    mma16816(acc[mt][nt], ah[mt], bl[nt]);
                    mma16816(acc[mt][nt], al[mt], bh[nt]);
                }
        }
        __syncthreads();
    }

#pragma unroll
    for (int mt = 0; mt < 2; mt++) {
        const int mA = m0 + warpM * 32 + mt * 16 + gid;
        const int mB = mA + 8;
        const float bA = bias[mA], bB = bias[mB];
#pragma unroll
        for (int nt = 0; nt < 8; nt++) {
            const int n0 = warpN * 64 + nt * 8 + tig * 2;
#pragma unroll
            for (int half = 0; half < 2; half++) {
                const int n = n0 + half;
                const float vA = tanhf(acc[mt][nt][half] * WINV + bA);
                const float vB = tanhf(acc[mt][nt][2 + half] * WINV + bB);
                if (out_f32) {
                    out_f32[(size_t)n * M_TOTAL + mA] = vA;
                    out_f32[(size_t)n * M_TOTAL + mB] = vB;
                }
                if (out_hi) {
                    const __half hA = __float2half_rn(vA);
                    const __half hB = __float2half_rn(vB);
                    out_hi[(size_t)n * M_TOTAL + mA] = hA;
                    out_lo[(size_t)n * M_TOTAL + mA] = __float2half_rn(vA - __half2float(hA));
                    out_hi[(size_t)n * M_TOTAL + mB] = hB;
                    out_lo[(size_t)n * M_TOTAL + mB] = __float2half_rn(vB - __half2float(hB));
                }
            }
        }
    }
}

// ---------------- fc3 (FFMA fp32) -------------------------------------------
__global__ void fc3_k(const float* __restrict__ A, const float* __restrict__ W,
                      const float* __restrict__ bias, float* __restrict__ P) {
    __shared__ float sh[2048];
    __shared__ float red[4][64];
    const int n = blockIdx.x;
    for (int i = threadIdx.x; i < 2048; i += blockDim.x) sh[i] = A[n * 2048 + i];
    __syncthreads();
    const int j = threadIdx.x & 63;
    const int c = threadIdx.x >> 6;
    float acc = 0.f;
    if (j < 62) {
        const int k0 = c * 512;
#pragma unroll 8
        for (int k = 0; k < 512; k++)
            acc = fmaf(sh[k0 + k], __ldg(W + (size_t)(k0 + k) * 62 + j), acc);
    }
    red[c][j] = acc;
    __syncthreads();
    if (c == 0 && j < 62)
        P[n * 62 + j] = red[0][j] + red[1][j] + red[2][j] + red[3][j] + bias[j];
}

// ---------------- trajectory ------------------------------------------------
__global__ void trajprep_k(const float* __restrict__ P, const float* __restrict__ dict,
                           int* __restrict__ segi, float* __restrict__ segf) {
    const int n = blockIdx.x * blockDim.x + threadIdx.x;
    if (n >= 128) return;
    const float* p = P + n * 62;
    float sx = p[0], sy = p[1];
    for (int s = 0; s < 20; s++) {
        float f = rintf(p[2 + 3 * s]);
        f = fminf(fmaxf(f, 0.f), 999.f);
        const int idx = (int)f;
        const float a = p[2 + 3 * s + 1], bb = p[2 + 3 * s + 2];
        segi[n * 20 + s] = idx;
        segf[(n * 20 + s) * 4 + 0] = a;
        segf[(n * 20 + s) * 4 + 1] = bb;
        segf[(n * 20 + s) * 4 + 2] = sx;
        segf[(n * 20 + s) * 4 + 3] = sy;
        sx = fmaf(dict[(idx * 200 + 199) * 2 + 0], a, sx);
        sy = fmaf(dict[(idx * 200 + 199) * 2 + 1], bb, sy);
    }
}

__global__ void traj_k(const float* __restrict__ dict, const int* __restrict__ segi,
                       const float* __restrict__ segf, float* __restrict__ out) {
    const int ns = blockIdx.x;
    const int l = threadIdx.x;
    if (l >= 200) return;
    const int idx = segi[ns];
    const float a = segf[ns * 4 + 0], bb = segf[ns * 4 + 1];
    const float sx = segf[ns * 4 + 2], sy = segf[ns * 4 + 3];
    const float2 base = reinterpret_cast<const float2*>(dict)[idx * 200 + l];
    float2 o;
    o.x = fmaf(base.x, a, sx);
    o.y = fmaf(base.y, bb, sy);
    reinterpret_cast<float2*>(out)[ns * 200 + l] = o;
}

// ---------------- launcher ---------------------------------------------------
extern "C" void kernel_launch(void* const* d_in, const int* in_sizes, int n_in,
                              void* d_out, int out_size) {
    const float* x   = (const float*)d_in[0];
    const float* w1  = (const float*)d_in[1];
    const float* b1  = (const float*)d_in[2];
    const float* w2  = (const float*)d_in[3];
    const float* b2  = (const float*)d_in[4];
    const float* w3  = (const float*)d_in[5];
    const float* b3  = (const float*)d_in[6];
    const float* w4  = (const float*)d_in[7];
    const float* b4  = (const float*)d_in[8];
    const float* fw1 = (const float*)d_in[9];
    const float* fb1 = (const float*)d_in[10];
    const float* fw2 = (const float*)d_in[11];
    const float* fb2 = (const float*)d_in[12];
    const float* fw3 = (const float*)d_in[13];
    const float* fb3 = (const float*)d_in[14];
    const float* dict = (const float*)d_in[15];
    float* out = (float*)d_out;

    __half *h1hi, *h1lo, *h2hi, *h2lo, *h3hi, *h3lo;
    __half *W2hi, *W2lo, *W3hi, *W3lo, *W4hi, *W4lo;
    __half *A1hi, *A1lo, *A2hi, *A2lo, *B0hi, *B0lo, *B1hi, *B1lo;
    float *pre2, *pre3, *pre4, *fcb, *p, *segf;
    int* segi;
    cudaGetSymbolAddress((void**)&h1hi, g_h1hi);
    cudaGetSymbolAddress((void**)&h1lo, g_h1lo);
    cudaGetSymbolAddress((void**)&h2hi, g_h2hi);
    cudaGetSymbolAddress((void**)&h2lo, g_h2lo);
    cudaGetSymbolAddress((void**)&h3hi, g_h3hi);
    cudaGetSymbolAddress((void**)&h3lo, g_h3lo);
    cudaGetSymbolAddress((void**)&W2hi, g_W2hi);
    cudaGetSymbolAddress((void**)&W2lo, g_W2lo);
    cudaGetSymbolAddress((void**)&W3hi, g_W3hi);
    cudaGetSymbolAddress((void**)&W3lo, g_W3lo);
    cudaGetSymbolAddress((void**)&W4hi, g_W4hi);
    cudaGetSymbolAddress((void**)&W4lo, g_W4lo);
    cudaGetSymbolAddress((void**)&pre2, g_pre2);
    cudaGetSymbolAddress((void**)&pre3, g_pre3);
    cudaGetSymbolAddress((void**)&pre4, g_pre4);
    cudaGetSymbolAddress((void**)&fcb,  g_fcb);
    cudaGetSymbolAddress((void**)&p,    g_p);
    cudaGetSymbolAddress((void**)&segi, g_segi);
    cudaGetSymbolAddress((void**)&segf, g_segf);
    cudaGetSymbolAddress((void**)&A1hi, g_A1hi);
    cudaGetSymbolAddress((void**)&A1lo, g_A1lo);
    cudaGetSymbolAddress((void**)&A2hi, g_A2hi);
    cudaGetSymbolAddress((void**)&A2lo, g_A2lo);
    cudaGetSymbolAddress((void**)&B0hi, g_B0hi);
    cudaGetSymbolAddress((void**)&B0lo, g_B0lo);
    cudaGetSymbolAddress((void**)&B1hi, g_B1hi);
    cudaGetSymbolAddress((void**)&B1lo, g_B1lo);

    cudaFuncSetAttribute(gemm_fc_mma<8192>, cudaFuncAttributeMaxDynamicSharedMemorySize, 73728);
    cudaFuncSetAttribute(gemm_fc_mma<2048>, cudaFuncAttributeMaxDynamicSharedMemorySize, 73728);
    cudaFuncSetAttribute((const void*)conv_mma_k<64, 49, 49, 47, 128>,
                         cudaFuncAttributeMaxDynamicSharedMemorySize, 73728);
    cudaFuncSetAttribute((const void*)conv_mma_k<128, 23, 23, 21, 256>,
                         cudaFuncAttributeMaxDynamicSharedMemorySize, 73728);
    cudaFuncSetAttribute((const void*)conv_mma_k<256, 10, 10, 8, 512>,
                         cudaFuncAttributeMaxDynamicSharedMemorySize, 73728);

    // conv1 (FFMA) -> h1 hi/lo
    conv1split_k<<<dim3((128 * 25 * 25 + 255) / 256, 16), 256>>>(x, w1, b1, h1hi, h1lo);
    // weight preps
    wsplitc_k<<<(128 * 576 + 255) / 256, 256>>>(w2, W2hi, W2lo, 128 * 576);
    wsplitc_k<<<(256 * 1152 + 255) / 256, 256>>>(w3, W3hi, W3lo, 256 * 1152);
    wsplitc_k<<<(512 * 2304 + 255) / 256, 256>>>(w4, W4hi, W4lo, 512 * 2304);
    wsplit_k<<<dim3(2048 / 32, 8192 / 32), dim3(32, 8)>>>(fw1, A1hi, A1lo, 8192, 2048);
    wsplit_k<<<dim3(2048 / 32, 2048 / 32), dim3(32, 8)>>>(fw2, A2hi, A2lo, 2048, 2048);

    // conv2: implicit GEMM (N = 128*47*47 = 282752 -> 2209 col-tiles)
    conv_mma_k<64, 49, 49, 47, 128><<<dim3(2209, 1), 256, 73728>>>(
        W2hi, W2lo, h1hi, h1lo, b2, pre2);
    poolsplit_k<128, 47, 23, 0><<<(128 * 128 * 23 * 23 + 255) / 256, 256>>>(pre2, h2hi, h2lo);
    // conv3 (N = 128*441 = 56448 -> 441 tiles, 2 m-tiles)
    conv_mma_k<128, 23, 23, 21, 256><<<dim3(441, 2), 256, 73728>>>(
        W3hi, W3lo, h2hi, h2lo, b3, pre3);
    poolsplit_k<256, 21, 10, 0><<<(128 * 256 * 10 * 10 + 255) / 256, 256>>>(pre3, h3hi, h3lo);
    // conv4 (N = 128*64 = 8192 -> 64 tiles, 4 m-tiles)
    conv_mma_k<256, 10, 10, 8, 512><<<dim3(64, 4), 256, 73728>>>(
        W4hi, W4lo, h3hi, h3lo, b4, pre4);
    poolsplit_k<512, 8, 4, 1><<<(128 * 512 * 4 * 4 + 255) / 256, 256>>>(pre4, B0hi, B0lo);

    // fc1 / fc2 (HMMA), fc3 (FFMA)
    gemm_fc_mma<8192><<<16, 256, 73728>>>(A1hi, A1lo, B0hi, B0lo, fb1, 2048,
                                          B1hi, B1lo, (float*)nullptr);
    gemm_fc_mma<2048><<<16, 256, 73728>>>(A2hi, A2lo, B1hi, B1lo, fb2, 2048,
                                          (__half*)nullptr, (__half*)nullptr, fcb);
    fc3_k<<<128, 256>>>(fcb, fw3, fb3, p);
    // trajectory
    trajprep_k<<<1, 128>>>(p, dict, segi, segf);
    traj_k<<<2560, 256>>>(dict, segi, segf, out);
}

// round 11
// speedup vs baseline: 2.2814x; 1.2854x over previous
#include <cuda_runtime.h>
#include <cuda_fp16.h>
#include <math.h>
#include <stdint.h>

#define WSCALE 1024.0f
#define WINV   (1.0f / 1024.0f)

// ---------------- scratch (static device globals) ---------------------------
__device__ __half2 g_h1i[128 * 64 * 49 * 49];    // conv1 out, (hi,lo) interleaved
__device__ __half2 g_h2i[128 * 128 * 23 * 23];   // conv2 out
__device__ __half2 g_h3i[128 * 256 * 10 * 10];   // conv3 out
__device__ __half g_W2hi[128 * 576],  g_W2lo[128 * 576];
__device__ __half g_W3hi[256 * 1152], g_W3lo[256 * 1152];
__device__ __half g_W4hi[512 * 2304], g_W4lo[512 * 2304];
__device__ float  g_fcb[128 * 2048];
__device__ float  g_p[128 * 62];
__device__ int    g_segi[128 * 20];
__device__ float  g_segf[128 * 20 * 4];
__device__ __half g_A1hi[2048 * 8192], g_A1lo[2048 * 8192];
__device__ __half g_A2hi[2048 * 2048], g_A2lo[2048 * 2048];
__device__ __half g_B0hi[128 * 8192],  g_B0lo[128 * 8192];
__device__ __half g_B1hi[128 * 2048],  g_B1lo[128 * 2048];

// ---------------- conv1 (IC=3, FFMA) + pool + relu + split ------------------
__global__ __launch_bounds__(256)
void conv1split_k(const float* __restrict__ in, const float* __restrict__ w,
                  const float* __restrict__ b, __half2* __restrict__ outi) {
    __shared__ float sw[108];
    const int ocg = blockIdx.y, tid = threadIdx.x;
    if (tid < 108) sw[tid] = w[ocg * 108 + tid];
    __syncthreads();
    const int item = blockIdx.x * 256 + tid;
    if (item >= 128 * 25 * 25) return;
    const int n = item / 625, r = item % 625;
    const int ty = r / 25, tx = r % 25;
    const int py0 = min(2 * ty, 47), px0 = min(2 * tx, 47);
    const int iy0 = 2 * py0, ix0 = 2 * px0;

    float acc[4][16];
#pragma unroll
    for (int o = 0; o < 4; o++) {
        const float bias = __ldg(b + ocg * 4 + o);
#pragma unroll
        for (int q = 0; q < 16; q++) acc[o][q] = bias;
    }
    const float* base = in + (size_t)n * 3 * 10000 + iy0 * 100 + ix0;
#pragma unroll
    for (int ic = 0; ic < 3; ic++) {
        float p[6][6];
        const float* bp = base + ic * 10000;
#pragma unroll
        for (int rr = 0; rr < 6; rr++) {
            const float* rp = bp + rr * 100;
            const float2 v0 = *reinterpret_cast<const float2*>(rp);
            const float2 v1 = *reinterpret_cast<const float2*>(rp + 2);
            const float2 v2 = *reinterpret_cast<const float2*>(rp + 4);
            p[rr][0] = v0.x; p[rr][1] = v0.y; p[rr][2] = v1.x;
            p[rr][3] = v1.y; p[rr][4] = v2.x; p[rr][5] = v2.y;
        }
#pragma unroll
        for (int o = 0; o < 4; o++) {
            const float* wp = sw + (o * 3 + ic) * 9;
#pragma unroll
            for (int ky = 0; ky < 3; ky++)
#pragma unroll
                for (int kx = 0; kx < 3; kx++) {
                    const float wv = wp[ky * 3 + kx];
#pragma unroll
                    for (int wy = 0; wy < 4; wy++)
#pragma unroll
                        for (int wx = 0; wx < 4; wx++)
                            acc[o][wy * 4 + wx] =
                                fmaf(p[wy + ky][wx + kx], wv, acc[o][wy * 4 + wx]);
                }
        }
    }
#pragma unroll
    for (int o = 0; o < 4; o++) {
        const int oc = ocg * 4 + o;
#pragma unroll
        for (int py = 0; py < 2; py++)
#pragma unroll
            for (int px = 0; px < 2; px++) {
                const float m = fmaxf(
                    fmaxf(acc[o][(2 * py) * 4 + 2 * px], acc[o][(2 * py) * 4 + 2 * px + 1]),
                    fmaxf(acc[o][(2 * py + 1) * 4 + 2 * px], acc[o][(2 * py + 1) * 4 + 2 * px + 1]));
                const float v = fmaxf(m, 0.f);
                const size_t addr = ((size_t)(n * 64 + oc) * 49 + py0 + py) * 49 + px0 + px;
                const __half h = __float2half_rn(v);
                outi[addr] = __halves2half2(h, __float2half_rn(v - __half2float(h)));
            }
    }
}

// ---------------- weight split (elementwise) --------------------------------
__global__ void wsplitc_k(const float* __restrict__ W, __half* __restrict__ hi,
                          __half* __restrict__ lo, int n) {
    const int i = blockIdx.x * 256 + threadIdx.x;
    if (i >= n) return;
    const float v = W[i] * WSCALE;
    const __half h = __float2half_rn(v);
    hi[i] = h;
    lo[i] = __float2half_rn(v - __half2float(h));
}

// ---------------- weight transpose + scale + split (FC) ---------------------
__global__ void wsplit_k(const float* __restrict__ W, __half* __restrict__ Ahi,
                         __half* __restrict__ Alo, int Kdim, int Mdim) {
    __shared__ float t[32][33];
    const int m0 = blockIdx.x * 32, k0 = blockIdx.y * 32;
    const int tx = threadIdx.x, ty = threadIdx.y;
#pragma unroll
    for (int j = 0; j < 4; j++)
        t[ty + 8 * j][tx] = W[(size_t)(k0 + ty + 8 * j) * Mdim + m0 + tx];
    __syncthreads();
#pragma unroll
    for (int j = 0; j < 4; j++) {
        const int m = m0 + ty + 8 * j, k = k0 + tx;
        const float v = t[tx][ty + 8 * j] * WSCALE;
        const __half hi = __float2half_rn(v);
        const __half lo = __float2half_rn(v - __half2float(hi));
        Ahi[(size_t)m * Kdim + k] = hi;
        Alo[(size_t)m * Kdim + k] = lo;
    }
}

// ---------------- mma.sync m16n8k16 wrapper ---------------------------------
__device__ __forceinline__ void mma16816(float* c, const uint32_t* a, const uint32_t* b) {
    asm volatile(
        "mma.sync.aligned.m16n8k16.row.col.f32.f16.f16.f32 "
        "{%0,%1,%2,%3}, {%4,%5,%6,%7}, {%8,%9}, {%0,%1,%2,%3};"
        : "+f"(c[0]), "+f"(c[1]), "+f"(c[2]), "+f"(c[3])
        : "r"(a[0]), "r"(a[1]), "r"(a[2]), "r"(a[3]), "r"(b[0]), "r"(b[1]));
}

// ---------------- implicit-GEMM conv + FUSED pool/relu/split ----------------
// Columns = (n, pooled_y, pooled_x, quadrant).  After GEMM, a 2x2 pool window
// is 4 adjacent columns; tig-parity shuffle completes the max in-register.
// SPLIT_OUT=0: write half2(hi,lo) at (n,oc,oy,ox). SPLIT_OUT=1: separate
// hi/lo arrays in fc layout [n][oc*OHH + p].
template <int IC, int IN_H, int OH, int OC, int SPLIT_OUT>
__global__ __launch_bounds__(256)
void conv_mma_pool_k(const __half* __restrict__ Whi, const __half* __restrict__ Wlo,
                     const __half2* __restrict__ ini, const float* __restrict__ bias,
                     __half2* __restrict__ outi, __half* __restrict__ outhi,
                     __half* __restrict__ outlo) {
    extern __shared__ __align__(16) char smem[];
    constexpr int K = IC * 9;
    constexpr int OHH = OH * OH;
    constexpr int TILE = 128 * 144;
    constexpr int ROWI4 = K / 8;
    constexpr int INHS = IN_H * IN_H;
    const int tid = threadIdx.x;
    const int wid = tid >> 5, lane = tid & 31;
    const int gid = lane >> 2, tig = lane & 3;
    const int warpM = wid & 3, warpN = wid >> 2;
    const int m0 = blockIdx.y * 128;

    __shared__ int s_bo[128];  // input base offset per col (q-quadrant pixel)
    __shared__ int s_po[128];  // pooled output base per col
    if (tid < 128) {
        const int col = blockIdx.x * 128 + tid;
        const int q = col & 3;
        const int pooled = col >> 2;
        const int n = pooled / OHH, prem = pooled % OHH;
        const int oy = prem / OH, ox = prem % OH;
        const int iy = 2 * oy + (q >> 1), ix = 2 * ox + (q & 1);
        s_bo[tid] = n * IC * INHS + iy * IN_H + ix;
        s_po[tid] = n * OC * OHH + prem;
    }
    __syncthreads();

    float acc[2][8][4];
#pragma unroll
    for (int mt = 0; mt < 2; mt++)
#pragma unroll
        for (int nt = 0; nt < 8; nt++)
#pragma unroll
            for (int q = 0; q < 4; q++) acc[mt][nt][q] = 0.f;

    const int4* Ah4 = reinterpret_cast<const int4*>(Whi) + (size_t)m0 * ROWI4;
    const int4* Al4 = reinterpret_cast<const int4*>(Wlo) + (size_t)m0 * ROWI4;

    const int jcol = tid & 127;           // B column owned by this thread
    const int t7 = tid >> 7;              // k-parity
    const int mybo = s_bo[jcol];
    const uint32_t bsw = 4u * ((uint32_t)(jcol >> 3) & 3u);  // B smem swizzle

    for (int ch = 0; ch < K / 64; ch++) {
        // A tiles: 128 rows x 8 int4 each (hi, lo)
#pragma unroll
        for (int j = 0; j < 4; j++) {
            const int u = j * 256 + tid;
            const int row = u >> 3, c = u & 7;
            *reinterpret_cast<int4*>(smem + 0 * TILE + row * 144 + c * 16) =
                Ah4[(size_t)row * ROWI4 + ch * 8 + c];
            *reinterpret_cast<int4*>(smem + 1 * TILE + row * 144 + c * 16) =
                Al4[(size_t)row * ROWI4 + ch * 8 + c];
        }
        // B tiles: inline im2col, interleaved half2 loads, swizzled 2B stores
        {
            int kk = ch * 64 + t7;
            int ic = kk / 9, r9 = kk % 9;
            int ky = r9 / 3, kx = r9 % 3;
            int kr = t7;
#pragma unroll
            for (int i = 0; i < 32; i++) {
                const __half2 v = ini[mybo + ic * INHS + ky * IN_H + kx];
                const uint32_t sw = ((uint32_t)(kr * 2)) ^ bsw;
                *reinterpret_cast<__half*>(smem + 2 * TILE + jcol * 144 + sw) = __low2half(v);
                *reinterpret_cast<__half*>(smem + 3 * TILE + jcol * 144 + sw) = __high2half(v);
                kr += 2;
                kx += 2;
                if (kx >= 3) { kx -= 3; ky += 1; }
                if (ky >= 3) { ky -= 3; ic += 1; }
            }
        }
        __syncthreads();

#pragma unroll
        for (int ks = 0; ks < 4; ks++) {
            uint32_t ah[2][4], al[2][4], bh[8][2], bl[8][2];
#pragma unroll
            for (int mt = 0; mt < 2; mt++) {
                const int row = warpM * 32 + mt * 16 + gid;
                const char* pA = smem + row * 144 + ks * 32 + tig * 4;
                ah[mt][0] = *reinterpret_cast<const uint32_t*>(pA);
                ah[mt][1] = *reinterpret_cast<const uint32_t*>(pA + 8 * 144);
                ah[mt][2] = *reinterpret_cast<const uint32_t*>(pA + 16);
                ah[mt][3] = *reinterpret_cast<const uint32_t*>(pA + 8 * 144 + 16);
                const char* pL = pA + TILE;
                al[mt][0] = *reinterpret_cast<const uint32_t*>(pL);
                al[mt][1] = *reinterpret_cast<const uint32_t*>(pL + 8 * 144);
                al[mt][2] = *reinterpret_cast<const uint32_t*>(pL + 16);
                al[mt][3] = *reinterpret_cast<const uint32_t*>(pL + 8 * 144 + 16);
            }
#pragma unroll
            for (int nt = 0; nt < 8; nt++) {
                const int col = warpN * 64 + nt * 8 + gid;
                const uint32_t sc = 4u * ((uint32_t)(col >> 3) & 3u);
                const uint32_t b0 = ((uint32_t)(ks * 32 + tig * 4)) ^ sc;
                const char* pB = smem + 2 * TILE + col * 144;
                bh[nt][0] = *reinterpret_cast<const uint32_t*>(pB + b0);
                bh[nt][1] = *reinterpret_cast<const uint32_t*>(pB + b0 + 16);
                bl[nt][0] = *reinterpret_cast<const uint32_t*>(pB + TILE + b0);
                bl[nt][1] = *reinterpret_cast<const uint32_t*>(pB + TILE + b0 + 16);
            }
#pragma unroll
            for (int mt = 0; mt < 2; mt++)
#pragma unroll
                for (int nt = 0; nt < 8; nt++) {
                    mma16816(acc[mt][nt], ah[mt], bh[nt]);
                    mma16816(acc[mt][nt], ah[mt], bl[nt]);
                    mma16816(acc[mt][nt], al[mt], bh[nt]);
                }
        }
        __syncthreads();
    }

    // fused pool + relu + split epilogue
#pragma unroll
    for (int mt = 0; mt < 2; mt++) {
        const int ocA = m0 + warpM * 32 + mt * 16 + gid;
        const int ocB = ocA + 8;
        const float bA = bias[ocA], bB = bias[ocB];
#pragma unroll
        for (int nt = 0; nt < 8; nt++) {
            const int col0 = warpN * 64 + nt * 8 + tig * 2;
            const float mA = fmaxf(acc[mt][nt][0], acc[mt][nt][1]);
            const float mB = fmaxf(acc[mt][nt][2], acc[mt][nt][3]);
            const float oA = __shfl_xor_sync(0xffffffffu, mA, 1);
            const float oB = __shfl_xor_sync(0xffffffffu, mB, 1);
            if ((tig & 1) == 0) {
                const float vA = fmaxf(fmaf(fmaxf(mA, oA), WINV, bA), 0.f);
                const float vB = fmaxf(fmaf(fmaxf(mB, oB), WINV, bB), 0.f);
                const int po = s_po[col0];
                const __half hA = __float2half_rn(vA);
                const __half hB = __float2half_rn(vB);
                if (SPLIT_OUT) {
                    outhi[po + ocA * OHH] = hA;
                    outlo[po + ocA * OHH] = __float2half_rn(vA - __half2float(hA));
                    outhi[po + ocB * OHH] = hB;
                    outlo[po + ocB * OHH] = __float2half_rn(vB - __half2float(hB));
                } else {
                    outi[po + ocA * OHH] =
                        __halves2half2(hA, __float2half_rn(vA - __half2float(hA)));
                    outi[po + ocB * OHH] =
                        __halves2half2(hB, __float2half_rn(vB - __half2float(hB)));
                }
            }
        }
    }
}

// ---------------- HMMA fp16-split FC GEMM (proven R5/R6 core) ---------------
template <int K>
__global__ __launch_bounds__(256)
void gemm_fc_mma(const __half* __restrict__ Ahi, const __half* __restrict__ Alo,
                 const __half* __restrict__ Bhi, const __half* __restrict__ Blo,
                 const float* __restrict__ bias, int M_TOTAL,
                 __half* __restrict__ out_hi, __half* __restrict__ out_lo,
                 float* __restrict__ out_f32) {
    extern __shared__ __align__(16) char smem[];
    constexpr int TILE = 128 * 144;
    constexpr int ROWI4 = K / 8;
    const int tid = threadIdx.x;
    const int wid = tid >> 5, lane = tid & 31;
    const int gid = lane >> 2, tig = lane & 3;
    const int warpM = wid & 3, warpN = wid >> 2;
    const int m0 = blockIdx.x * 128;

    const int4* srcs[4] = {
        reinterpret_cast<const int4*>(Ahi) + (size_t)m0 * ROWI4,
        reinterpret_cast<const int4*>(Alo) + (size_t)m0 * ROWI4,
        reinterpret_cast<const int4*>(Bhi),
        reinterpret_cast<const int4*>(Blo)};

    float acc[2][8][4];
#pragma unroll
    for (int mt = 0; mt < 2; mt++)
#pragma unroll
        for (int nt = 0; nt < 8; nt++)
#pragma unroll
            for (int q = 0; q < 4; q++) acc[mt][nt][q] = 0.f;

    for (int ch = 0; ch < K / 64; ch++) {
#pragma unroll
        for (int r = 0; r < 4; r++) {
            const int4* src = srcs[r] + ch * 8;
#pragma unroll
            for (int j = 0; j < 4; j++) {
                const int u = j * 256 + tid;
                const int row = u >> 3, c = u & 7;
                *reinterpret_cast<int4*>(smem + r * TILE + row * 144 + c * 16) =
                    src[(size_t)row * ROWI4 + c];
            }
        }
        __syncthreads();

#pragma unroll
        for (int ks = 0; ks < 4; ks++) {
            uint32_t ah[2][4], al[2][4], bh[8][2], bl[8][2];
#pragma unroll
            for (int mt = 0; mt < 2; mt++) {
                const int row = warpM * 32 + mt * 16 + gid;
                const char* pA = smem + row * 144 + ks * 32 + tig * 4;
                ah[mt][0] = *reinterpret_cast<const uint32_t*>(pA);
                ah[mt][1] = *reinterpret_cast<const uint32_t*>(pA + 8 * 144);
                ah[mt][2] = *reinterpret_cast<const uint32_t*>(pA + 16);
                ah[mt][3] = *reinterpret_cast<const uint32_t*>(pA + 8 * 144 + 16);
                const char* pL = pA + TILE;
                al[mt][0] = *reinterpret_cast<const uint32_t*>(pL);
                al[mt][1] = *reinterpret_cast<const uint32_t*>(pL + 8 * 144);
                al[mt][2] = *reinterpret_cast<const uint32_t*>(pL + 16);
                al[mt][3] = *reinterpret_cast<const uint32_t*>(pL + 8 * 144 + 16);
            }
#pragma unroll
            for (int nt = 0; nt < 8; nt++) {
                const int n = warpN * 64 + nt * 8 + gid;
                const char* pB = smem + 2 * TILE + n * 144 + ks * 32 + tig * 4;
                bh[nt][0] = *reinterpret_cast<const uint32_t*>(pB);
                bh[nt][1] = *reinterpret_cast<const uint32_t*>(pB + 16);
                bl[nt][0] = *reinterpret_cast<const uint32_t*>(pB + TILE);
                bl[nt][1] = *reinterpret_cast<const uint32_t*>(pB + TILE + 16);
            }
#pragma unroll
            for (int mt = 0; mt < 2; mt++)
#pragma unroll
                for (int nt = 0; nt < 8; nt++) {
                    mma16816(acc[mt][nt], ah[mt], bh[nt]);
                    mma16816(acc[mt][nt], ah[mt], bl[nt]);
                    mma16816(acc[mt][nt], al[mt], bh[nt]);
                }
        }
        __syncthreads();
    }

#pragma unroll
    for (int mt = 0; mt < 2; mt++) {
        const int mA = m0 + warpM * 32 + mt * 16 + gid;
        const int mB = mA + 8;
        const float bA = bias[mA], bB = bias[mB];
#pragma unroll
        for (int nt = 0; nt < 8; nt++) {
            const int n0 = warpN * 64 + nt * 8 + tig * 2;
#pragma unroll
            for (int half = 0; half < 2; half++) {
                const int n = n0 + half;
                const float vA = tanhf(acc[mt][nt][half] * WINV + bA);
                const float vB = tanhf(acc[mt][nt][2 + half] * WINV + bB);
                if (out_f32) {
                    out_f32[(size_t)n * M_TOTAL + mA] = vA;
                    out_f32[(size_t)n * M_TOTAL + mB] = vB;
                }
                if (out_hi) {
                    const __half hA = __float2half_rn(vA);
                    const __half hB = __float2half_rn(vB);
                    out_hi[(size_t)n * M_TOTAL + mA] = hA;
                    out_lo[(size_t)n * M_TOTAL + mA] = __float2half_rn(vA - __half2float(hA));
                    out_hi[(size_t)n * M_TOTAL + mB] = hB;
                    out_lo[(size_t)n * M_TOTAL + mB] = __float2half_rn(vB - __half2float(hB));
                }
            }
        }
    }
}

// ---------------- fc3 (FFMA fp32) -------------------------------------------
__global__ void fc3_k(const float* __restrict__ A, const float* __restrict__ W,
                      const float* __restrict__ bias, float* __restrict__ P) {
    __shared__ float sh[2048];
    __shared__ float red[4][64];
    const int n = blockIdx.x;
    for (int i = threadIdx.x; i < 2048; i += blockDim.x) sh[i] = A[n * 2048 + i];
    __syncthreads();
    const int j = threadIdx.x & 63;
    const int c = threadIdx.x >> 6;
    float acc = 0.f;
    if (j < 62) {
        const int k0 = c * 512;
#pragma unroll 8
        for (int k = 0; k < 512; k++)
            acc = fmaf(sh[k0 + k], __ldg(W + (size_t)(k0 + k) * 62 + j), acc);
    }
    red[c][j] = acc;
    __syncthreads();
    if (c == 0 && j < 62)
        P[n * 62 + j] = red[0][j] + red[1][j] + red[2][j] + red[3][j] + bias[j];
}

// ---------------- trajectory ------------------------------------------------
__global__ void trajprep_k(const float* __restrict__ P, const float* __restrict__ dict,
                           int* __restrict__ segi, float* __restrict__ segf) {
    const int n = blockIdx.x * blockDim.x + threadIdx.x;
    if (n >= 128) return;
    const float* p = P + n * 62;
    float sx = p[0], sy = p[1];
    for (int s = 0; s < 20; s++) {
        float f = rintf(p[2 + 3 * s]);
        f = fminf(fmaxf(f, 0.f), 999.f);
        const int idx = (int)f;
        const float a = p[2 + 3 * s + 1], bb = p[2 + 3 * s + 2];
        segi[n * 20 + s] = idx;
        segf[(n * 20 + s) * 4 + 0] = a;
        segf[(n * 20 + s) * 4 + 1] = bb;
        segf[(n * 20 + s) * 4 + 2] = sx;
        segf[(n * 20 + s) * 4 + 3] = sy;
        sx = fmaf(dict[(idx * 200 + 199) * 2 + 0], a, sx);
        sy = fmaf(dict[(idx * 200 + 199) * 2 + 1], bb, sy);
    }
}

__global__ void traj_k(const float* __restrict__ dict, const int* __restrict__ segi,
                       const float* __restrict__ segf, float* __restrict__ out) {
    const int ns = blockIdx.x;
    const int l = threadIdx.x;
    if (l >= 200) return;
    const int idx = segi[ns];
    const float a = segf[ns * 4 + 0], bb = segf[ns * 4 + 1];
    const float sx = segf[ns * 4 + 2], sy = segf[ns * 4 + 3];
    const float2 base = reinterpret_cast<const float2*>(dict)[idx * 200 + l];
    float2 o;
    o.x = fmaf(base.x, a, sx);
    o.y = fmaf(base.y, bb, sy);
    reinterpret_cast<float2*>(out)[ns * 200 + l] = o;
}

// ---------------- launcher ---------------------------------------------------
extern "C" void kernel_launch(void* const* d_in, const int* in_sizes, int n_in,
                              void* d_out, int out_size) {
    const float* x   = (const float*)d_in[0];
    const float* w1  = (const float*)d_in[1];
    const float* b1  = (const float*)d_in[2];
    const float* w2  = (const float*)d_in[3];
    const float* b2  = (const float*)d_in[4];
    const float* w3  = (const float*)d_in[5];
    const float* b3  = (const float*)d_in[6];
    const float* w4  = (const float*)d_in[7];
    const float* b4  = (const float*)d_in[8];
    const float* fw1 = (const float*)d_in[9];
    const float* fb1 = (const float*)d_in[10];
    const float* fw2 = (const float*)d_in[11];
    const float* fb2 = (const float*)d_in[12];
    const float* fw3 = (const float*)d_in[13];
    const float* fb3 = (const float*)d_in[14];
    const float* dict = (const float*)d_in[15];
    float* out = (float*)d_out;

    __half2 *h1i, *h2i, *h3i;
    __half *W2hi, *W2lo, *W3hi, *W3lo, *W4hi, *W4lo;
    __half *A1hi, *A1lo, *A2hi, *A2lo, *B0hi, *B0lo, *B1hi, *B1lo;
    float *fcb, *p, *segf;
    int* segi;
    cudaGetSymbolAddress((void**)&h1i, g_h1i);
    cudaGetSymbolAddress((void**)&h2i, g_h2i);
    cudaGetSymbolAddress((void**)&h3i, g_h3i);
    cudaGetSymbolAddress((void**)&W2hi, g_W2hi);
    cudaGetSymbolAddress((void**)&W2lo, g_W2lo);
    cudaGetSymbolAddress((void**)&W3hi, g_W3hi);
    cudaGetSymbolAddress((void**)&W3lo, g_W3lo);
    cudaGetSymbolAddress((void**)&W4hi, g_W4hi);
    cudaGetSymbolAddress((void**)&W4lo, g_W4lo);
    cudaGetSymbolAddress((void**)&fcb,  g_fcb);
    cudaGetSymbolAddress((void**)&p,    g_p);
    cudaGetSymbolAddress((void**)&segi, g_segi);
    cudaGetSymbolAddress((void**)&segf, g_segf);
    cudaGetSymbolAddress((void**)&A1hi, g_A1hi);
    cudaGetSymbolAddress((void**)&A1lo, g_A1lo);
    cudaGetSymbolAddress((void**)&A2hi, g_A2hi);
    cudaGetSymbolAddress((void**)&A2lo, g_A2lo);
    cudaGetSymbolAddress((void**)&B0hi, g_B0hi);
    cudaGetSymbolAddress((void**)&B0lo, g_B0lo);
    cudaGetSymbolAddress((void**)&B1hi, g_B1hi);
    cudaGetSymbolAddress((void**)&B1lo, g_B1lo);

    cudaFuncSetAttribute(gemm_fc_mma<8192>, cudaFuncAttributeMaxDynamicSharedMemorySize, 73728);
    cudaFuncSetAttribute(gemm_fc_mma<2048>, cudaFuncAttributeMaxDynamicSharedMemorySize, 73728);
    cudaFuncSetAttribute((const void*)conv_mma_pool_k<64, 49, 23, 128, 0>,
                         cudaFuncAttributeMaxDynamicSharedMemorySize, 73728);
    cudaFuncSetAttribute((const void*)conv_mma_pool_k<128, 23, 10, 256, 0>,
                         cudaFuncAttributeMaxDynamicSharedMemorySize, 73728);
    cudaFuncSetAttribute((const void*)conv_mma_pool_k<256, 10, 4, 512, 1>,
                         cudaFuncAttributeMaxDynamicSharedMemorySize, 73728);

    // conv1 (FFMA) -> h1 interleaved
    conv1split_k<<<dim3((128 * 25 * 25 + 255) / 256, 16), 256>>>(x, w1, b1, h1i);
    // weight preps
    wsplitc_k<<<(128 * 576 + 255) / 256, 256>>>(w2, W2hi, W2lo, 128 * 576);
    wsplitc_k<<<(256 * 1152 + 255) / 256, 256>>>(w3, W3hi, W3lo, 256 * 1152);
    wsplitc_k<<<(512 * 2304 + 255) / 256, 256>>>(w4, W4hi, W4lo, 512 * 2304);
    wsplit_k<<<dim3(2048 / 32, 8192 / 32), dim3(32, 8)>>>(fw1, A1hi, A1lo, 8192, 2048);
    wsplit_k<<<dim3(2048 / 32, 2048 / 32), dim3(32, 8)>>>(fw2, A2hi, A2lo, 2048, 2048);

    // conv2: NCOL = 128*23*23*4 = 270848 -> 2116 tiles
    conv_mma_pool_k<64, 49, 23, 128, 0><<<dim3(2116, 1), 256, 73728>>>(
        W2hi, W2lo, h1i, b2, h2i, nullptr, nullptr);
    // conv3: NCOL = 128*10*10*4 = 51200 -> 400 tiles, 2 m-tiles
    conv_mma_pool_k<128, 23, 10, 256, 0><<<dim3(400, 2), 256, 73728>>>(
        W3hi, W3lo, h2i, b3, h3i, nullptr, nullptr);
    // conv4: NCOL = 128*4*4*4 = 8192 -> 64 tiles, 4 m-tiles; out = fc1 B0 split
    conv_mma_pool_k<256, 10, 4, 512, 1><<<dim3(64, 4), 256, 73728>>>(
        W4hi, W4lo, h3i, b4, nullptr, B0hi, B0lo);

    // fc1 / fc2 (HMMA), fc3 (FFMA)
    gemm_fc_mma<8192><<<16, 256, 73728>>>(A1hi, A1lo, B0hi, B0lo, fb1, 2048,
                                          B1hi, B1lo, (float*)nullptr);
    gemm_fc_mma<2048><<<16, 256, 73728>>>(A2hi, A2lo, B1hi, B1lo, fb2, 2048,
                                          (__half*)nullptr, (__half*)nullptr, fcb);
    fc3_k<<<128, 256>>>(fcb, fw3, fb3, p);
    // trajectory
    trajprep_k<<<1, 128>>>(p, dict, segi, segf);
    traj_k<<<2560, 256>>>(dict, segi, segf, out);
}